// round 7
// baseline (speedup 1.0000x reference)
#include <cuda_runtime.h>
#include <cstdio>

#define Hh  8
#define Dd  256
#define HDe 32
#define Bb  16
#define Qq  512
#define S1c 64
#define Tt  448

typedef unsigned long long u64;

// ---- packed f32x2 helpers (FFMA2 is PTX-only) ----
__device__ __forceinline__ u64 pk2(float x, float y) {
    u64 r; asm("mov.b64 %0, {%1, %2};" : "=l"(r) : "f"(x), "f"(y)); return r;
}
__device__ __forceinline__ float2 up2(u64 v) {
    float2 r; asm("mov.b64 {%0, %1}, %2;" : "=f"(r.x), "=f"(r.y) : "l"(v)); return r;
}
__device__ __forceinline__ u64 fma2(u64 a, u64 b, u64 c) {
    u64 d; asm("fma.rn.f32x2 %0, %1, %2, %3;" : "=l"(d) : "l"(a), "l"(b), "l"(c)); return d;
}

// ---------------- static scratch ----------------
__device__ float g_Qt1[Hh*Bb*Tt*HDe];
__device__ float g_Qt [Hh*Bb*Tt*HDe];
__device__ float g_Kc [Hh*Bb*Tt*HDe];
__device__ float g_Vc [Hh*Bb*Tt*HDe];
__device__ float g_Qs [Hh*Bb*S1c*HDe];
__device__ float g_Ks [Hh*Bb*S1c*HDe];
__device__ float g_Vs [Hh*Bb*S1c*HDe];
__device__ float g_P1 [Hh*Bb*Tt*Tt];
__device__ float g_P2 [Hh*Bb*Tt*S1c];
__device__ float g_P3 [Hh*Bb*S1c*Tt];
__device__ float g_heads[Bb*Qq*Dd];      // [b][q][h][e]

struct ProjArgs {
    const float* W[4];
    float*       O[4];
};

// Dup-A row stride: 128 data floats + 4 pad (16B-aligned rows, conflict-free reads)
#define DSTR 132

// ============= projection GEMM: X[token,256] x Wcat[256,256] -> O =============
// 64x64 tile, 128 threads, 4m x 8n per thread. A duplicated in smem (slow side).
__global__ __launch_bounds__(128) void proj_kernel(
    const float* __restrict__ X, ProjArgs args, int TL, int qoff)
{
    __shared__ __align__(16) float Asd[32][DSTR];  // [k][m dup]
    __shared__ __align__(16) float Bs [32][64];    // [k][n]
    const int sel = blockIdx.y >> 2;
    const int n0  = (blockIdx.y & 3) * 64;
    const int m0  = blockIdx.x * 64;
    const float* __restrict__ W = args.W[sel];
    float* __restrict__ O = args.O[sel];
    const int tid = threadIdx.x;
    const int tx = tid & 7;     // n-thread (8 cols each)
    const int ty = tid >> 3;    // m-thread (4 rows each)

    // fill identity: one token row per thread-pair
    const int fr    = tid >> 1;          // 0..63 token row in tile
    const int khalf = (tid & 1) * 16;    // k half
    int t = m0 + fr;
    int fb = t / TL, fn = t - fb * TL;
    const size_t arow = (size_t)(fb * Qq + qoff + fn) * Dd;

    u64 acc[4][4];
#pragma unroll
    for (int i = 0; i < 4; i++)
#pragma unroll
        for (int j = 0; j < 4; j++) acc[i][j] = 0ull;

    for (int k0 = 0; k0 < Dd; k0 += 32) {
        // A: load 4 float4 (64B run) per thread, store duplicated
#pragma unroll
        for (int i = 0; i < 4; i++) {
            int kq = khalf + i * 4;
            float4 v = *(const float4*)(X + arow + k0 + kq);
            *(u64*)&Asd[kq + 0][2 * fr] = pk2(v.x, v.x);
            *(u64*)&Asd[kq + 1][2 * fr] = pk2(v.y, v.y);
            *(u64*)&Asd[kq + 2][2 * fr] = pk2(v.z, v.z);
            *(u64*)&Asd[kq + 3][2 * fr] = pk2(v.w, v.w);
        }
        // B: Wcat[k][c] with c=(h,e) remap; 4 float4 per thread
#pragma unroll
        for (int i = 0; i < 4; i++) {
            int lin = tid + i * 128;
            int kk = lin >> 4;
            int nq = (lin & 15) << 2;
            int c = n0 + nq;
            int h = c >> 5, e = c & 31;
            *(float4*)&Bs[kk][nq] =
                *(const float4*)(W + (size_t)h * (Dd * HDe) + (k0 + kk) * HDe + e);
        }
        __syncthreads();
#pragma unroll
        for (int kk = 0; kk < 32; kk++) {
            ulonglong2 am01 = *(const ulonglong2*)&Asd[kk][ty * 8];
            ulonglong2 am23 = *(const ulonglong2*)&Asd[kk][ty * 8 + 4];
            ulonglong2 bn01 = *(const ulonglong2*)&Bs[kk][tx * 8];
            ulonglong2 bn23 = *(const ulonglong2*)&Bs[kk][tx * 8 + 4];
            acc[0][0] = fma2(am01.x, bn01.x, acc[0][0]);
            acc[0][1] = fma2(am01.x, bn01.y, acc[0][1]);
            acc[0][2] = fma2(am01.x, bn23.x, acc[0][2]);
            acc[0][3] = fma2(am01.x, bn23.y, acc[0][3]);
            acc[1][0] = fma2(am01.y, bn01.x, acc[1][0]);
            acc[1][1] = fma2(am01.y, bn01.y, acc[1][1]);
            acc[1][2] = fma2(am01.y, bn23.x, acc[1][2]);
            acc[1][3] = fma2(am01.y, bn23.y, acc[1][3]);
            acc[2][0] = fma2(am23.x, bn01.x, acc[2][0]);
            acc[2][1] = fma2(am23.x, bn01.y, acc[2][1]);
            acc[2][2] = fma2(am23.x, bn23.x, acc[2][2]);
            acc[2][3] = fma2(am23.x, bn23.y, acc[2][3]);
            acc[3][0] = fma2(am23.y, bn01.x, acc[3][0]);
            acc[3][1] = fma2(am23.y, bn01.y, acc[3][1]);
            acc[3][2] = fma2(am23.y, bn23.x, acc[3][2]);
            acc[3][3] = fma2(am23.y, bn23.y, acc[3][3]);
        }
        __syncthreads();
    }
    // epilogue: cols c0..c0+7 within one head (n0%64==0, tx*8<=56 -> e+7<=31)
    const int c0 = n0 + tx * 8;
    const int h = c0 >> 5, e = c0 & 31;
#pragma unroll
    for (int i = 0; i < 4; i++) {
        int tt = m0 + ty * 4 + i;
        int b = tt / TL, n = tt - b * TL;
        float2 p0 = up2(acc[i][0]), p1 = up2(acc[i][1]);
        float2 p2 = up2(acc[i][2]), p3 = up2(acc[i][3]);
        float* dst = O + (((size_t)h * Bb + b) * TL + n) * HDe + e;
        *(float4*)dst       = make_float4(p0.x, p0.y, p1.x, p1.y);
        *(float4*)(dst + 4) = make_float4(p2.x, p2.y, p3.x, p3.y);
    }
}

// ============= batched QK^T: S[n,m] = Q[n,:]·K[m,:], K=32 =============
__global__ __launch_bounds__(128) void qk_kernel(
    const float* __restrict__ Qm, const float* __restrict__ Km,
    float* __restrict__ S, int Nq, int Nk)
{
    __shared__ __align__(16) float Qsd[32][DSTR];  // [e][query dup]
    __shared__ __align__(16) float Ks [32][64];    // [e][key]
    const int z = blockIdx.z;
    const float* Qb = Qm + (size_t)z * Nq * HDe;
    const float* Kb = Km + (size_t)z * Nk * HDe;
    float* Sb = S + (size_t)z * Nq * Nk;
    const int mq0 = blockIdx.y * 64;   // query tile
    const int mk0 = blockIdx.x * 64;   // key tile
    const int tid = threadIdx.x;
    const int fr    = tid >> 1;
    const int ehalf = (tid & 1) * 16;
#pragma unroll
    for (int i = 0; i < 4; i++) {
        int eq = ehalf + i * 4;
        float4 v = *(const float4*)(Qb + (size_t)(mq0 + fr) * HDe + eq);
        *(u64*)&Qsd[eq + 0][2 * fr] = pk2(v.x, v.x);
        *(u64*)&Qsd[eq + 1][2 * fr] = pk2(v.y, v.y);
        *(u64*)&Qsd[eq + 2][2 * fr] = pk2(v.z, v.z);
        *(u64*)&Qsd[eq + 3][2 * fr] = pk2(v.w, v.w);
        float4 w = *(const float4*)(Kb + (size_t)(mk0 + fr) * HDe + eq);
        Ks[eq + 0][fr] = w.x; Ks[eq + 1][fr] = w.y;
        Ks[eq + 2][fr] = w.z; Ks[eq + 3][fr] = w.w;
    }
    __syncthreads();
    const int tx = tid & 7;     // key-thread (8 keys)
    const int ty = tid >> 3;    // query-thread (4 queries)
    u64 acc[4][4];
#pragma unroll
    for (int i = 0; i < 4; i++)
#pragma unroll
        for (int j = 0; j < 4; j++) acc[i][j] = 0ull;
#pragma unroll
    for (int e = 0; e < 32; e++) {
        ulonglong2 am01 = *(const ulonglong2*)&Qsd[e][ty * 8];
        ulonglong2 am23 = *(const ulonglong2*)&Qsd[e][ty * 8 + 4];
        ulonglong2 bn01 = *(const ulonglong2*)&Ks[e][tx * 8];
        ulonglong2 bn23 = *(const ulonglong2*)&Ks[e][tx * 8 + 4];
        acc[0][0] = fma2(am01.x, bn01.x, acc[0][0]);
        acc[0][1] = fma2(am01.x, bn01.y, acc[0][1]);
        acc[0][2] = fma2(am01.x, bn23.x, acc[0][2]);
        acc[0][3] = fma2(am01.x, bn23.y, acc[0][3]);
        acc[1][0] = fma2(am01.y, bn01.x, acc[1][0]);
        acc[1][1] = fma2(am01.y, bn01.y, acc[1][1]);
        acc[1][2] = fma2(am01.y, bn23.x, acc[1][2]);
        acc[1][3] = fma2(am01.y, bn23.y, acc[1][3]);
        acc[2][0] = fma2(am23.x, bn01.x, acc[2][0]);
        acc[2][1] = fma2(am23.x, bn01.y, acc[2][1]);
        acc[2][2] = fma2(am23.x, bn23.x, acc[2][2]);
        acc[2][3] = fma2(am23.x, bn23.y, acc[2][3]);
        acc[3][0] = fma2(am23.y, bn01.x, acc[3][0]);
        acc[3][1] = fma2(am23.y, bn01.y, acc[3][1]);
        acc[3][2] = fma2(am23.y, bn23.x, acc[3][2]);
        acc[3][3] = fma2(am23.y, bn23.y, acc[3][3]);
    }
#pragma unroll
    for (int i = 0; i < 4; i++) {
        float2 p0 = up2(acc[i][0]), p1 = up2(acc[i][1]);
        float2 p2 = up2(acc[i][2]), p3 = up2(acc[i][3]);
        float* row = Sb + (size_t)(mq0 + ty * 4 + i) * Nk + mk0 + tx * 8;
        *(float4*)row       = make_float4(p0.x, p0.y, p1.x, p1.y);
        *(float4*)(row + 4) = make_float4(p2.x, p2.y, p3.x, p3.y);
    }
}

// ============= fuse MLP + softmax (R4 version, best known) =============
template<int NK, int QPB>
__global__ __launch_bounds__(256) void fuse_softmax_kernel(
    float* __restrict__ S, const float* __restrict__ aux,
    const float* __restrict__ W1, const float* __restrict__ b1,
    const float* __restrict__ W2, const float* __restrict__ b2,
    int Nq, int qn_off, int qm_off)
{
    __shared__ __align__(16) u64 sW1d[16][16];
    __shared__ __align__(16) u64 sW2d[16][8];
    __shared__ u64 sb1d[16], sb2d[8];
    __shared__ __align__(16) float fs[QPB][8][NK];
    const int tid = threadIdx.x;
    { int j = tid >> 4, c = tid & 15; float w = W1[c * 16 + j]; sW1d[j][c] = pk2(w, w); }
    if (tid < 128) { int j = tid >> 3, h = tid & 7; float w = W2[j * 8 + h]; sW2d[j][h] = pk2(w, w); }
    if (tid < 16)  { float w = b1[tid]; sb1d[tid] = pk2(w, w); }
    if (tid < 8)   { float w = b2[tid]; sb2d[tid] = pk2(w, w); }
    __syncthreads();

    const int nblocks = Nq / QPB;
    const int nb = blockIdx.x % nblocks;
    const int b  = blockIdx.x / nblocks;
    constexpr int TPQ = 256 / QPB;
    const int ql = tid / TPQ;
    const int tl = tid % TPQ;
    const int n  = nb * QPB + ql;
    const int m0 = tl * 4;

    if (m0 < NK) {
        u64 x2[16][2];
#pragma unroll
        for (int h = 0; h < 8; h++) {
            ulonglong2 v = *(const ulonglong2*)(S + ((size_t)(h * Bb + b) * Nq + n) * NK + m0);
            x2[h][0] = v.x; x2[h][1] = v.y;
            ulonglong2 w = *(const ulonglong2*)(aux + ((size_t)(h * Bb + b) * Qq + qn_off + n) * Qq + qm_off + m0);
            x2[8 + h][0] = w.x; x2[8 + h][1] = w.y;
        }
        u64 f0[8], f1[8];
#pragma unroll
        for (int h = 0; h < 8; h++) { f0[h] = sb2d[h]; f1[h] = f0[h]; }
#pragma unroll
        for (int j = 0; j < 16; j++) {
            u64 h0 = sb1d[j], h1 = h0;
            ulonglong2 w1p[8];
#pragma unroll
            for (int p = 0; p < 8; p++) w1p[p] = *(const ulonglong2*)&sW1d[j][p * 2];
#pragma unroll
            for (int c = 0; c < 16; c++) {
                u64 wv = (c & 1) ? w1p[c >> 1].y : w1p[c >> 1].x;
                h0 = fma2(x2[c][0], wv, h0);
                h1 = fma2(x2[c][1], wv, h1);
            }
            float2 ra = up2(h0), rb = up2(h1);
            ra.x = fmaxf(ra.x, 0.f); ra.y = fmaxf(ra.y, 0.f);
            rb.x = fmaxf(rb.x, 0.f); rb.y = fmaxf(rb.y, 0.f);
            u64 r0 = pk2(ra.x, ra.y), r1 = pk2(rb.x, rb.y);
            ulonglong2 w2p[4];
#pragma unroll
            for (int p = 0; p < 4; p++) w2p[p] = *(const ulonglong2*)&sW2d[j][p * 2];
#pragma unroll
            for (int h = 0; h < 8; h++) {
                u64 wv = (h & 1) ? w2p[h >> 1].y : w2p[h >> 1].x;
                f0[h] = fma2(r0, wv, f0[h]);
                f1[h] = fma2(r1, wv, f1[h]);
            }
        }
#pragma unroll
        for (int h = 0; h < 8; h++) {
            ulonglong2 st; st.x = f0[h]; st.y = f1[h];
            *(ulonglong2*)&fs[ql][h][m0] = st;
        }
    }
    __syncthreads();

    const int warp = tid >> 5, lane = tid & 31;
    constexpr int R = QPB * 8;
    for (int row = warp; row < R; row += 8) {
        int qr = row >> 3;
        int hr = row & 7;
        float* frow = fs[qr][hr];
        float mx = -3.0e38f;
        for (int m = lane; m < NK; m += 32) mx = fmaxf(mx, frow[m]);
#pragma unroll
        for (int o = 16; o > 0; o >>= 1) mx = fmaxf(mx, __shfl_xor_sync(0xffffffffu, mx, o));
        float sum = 0.f;
        for (int m = lane; m < NK; m += 32) {
            float ev = __expf(frow[m] - mx);
            frow[m] = ev;
            sum += ev;
        }
#pragma unroll
        for (int o = 16; o > 0; o >>= 1) sum += __shfl_xor_sync(0xffffffffu, sum, o);
        float inv = 1.f / sum;
        float* Srow = S + ((size_t)(hr * Bb + b) * Nq + nb * QPB + qr) * NK;
        for (int m = lane; m < NK; m += 32) Srow[m] = frow[m] * inv;
    }
}

// ============= batched AV: O[n,e] = sum_m P[n,m] V[m,e] =============
// 128 threads, 64n tile, 4n x 4e per thread; P duplicated (slow side), V natural u64.
__global__ __launch_bounds__(128) void av_kernel(
    const float* __restrict__ P, const float* __restrict__ V,
    float* __restrict__ heads, int Nq, int Nk, int qoff, int accum)
{
    __shared__ __align__(16) float Psd[32][DSTR];  // [m][n dup]
    __shared__ __align__(16) float Vs [32][32];    // [m][e]
    const int z = blockIdx.z;
    const int h = z >> 4, b = z & 15;
    const float* Pb = P + (size_t)z * Nq * Nk;
    const float* Vb = V + (size_t)z * Nk * HDe;
    const int n0 = blockIdx.y * 64;
    const int tid = threadIdx.x;
    const int tx = tid & 7;     // e-thread: 4 e each
    const int ty = tid >> 3;    // n-thread: 4 n each
    const int fr    = tid >> 1;         // n row for P fill
    const int mhalf = (tid & 1) * 16;
    u64 acc[4][2];
#pragma unroll
    for (int i = 0; i < 4; i++) { acc[i][0] = 0ull; acc[i][1] = 0ull; }

    for (int k0 = 0; k0 < Nk; k0 += 32) {
#pragma unroll
        for (int i = 0; i < 4; i++) {
            int mq = mhalf + i * 4;
            float4 v = *(const float4*)(Pb + (size_t)(n0 + fr) * Nk + k0 + mq);
            *(u64*)&Psd[mq + 0][2 * fr] = pk2(v.x, v.x);
            *(u64*)&Psd[mq + 1][2 * fr] = pk2(v.y, v.y);
            *(u64*)&Psd[mq + 2][2 * fr] = pk2(v.z, v.z);
            *(u64*)&Psd[mq + 3][2 * fr] = pk2(v.w, v.w);
        }
        // V: straight copy 32x32
#pragma unroll
        for (int i = 0; i < 2; i++) {
            int lin = tid + i * 128;
            *(float4*)((float*)Vs + lin * 4) = *(const float4*)(Vb + (size_t)k0 * HDe + lin * 4);
        }
        __syncthreads();
#pragma unroll
        for (int kk = 0; kk < 32; kk++) {
            ulonglong2 an01 = *(const ulonglong2*)&Psd[kk][ty * 8];
            ulonglong2 an23 = *(const ulonglong2*)&Psd[kk][ty * 8 + 4];
            ulonglong2 ve   = *(const ulonglong2*)&Vs[kk][tx * 4];
            acc[0][0] = fma2(an01.x, ve.x, acc[0][0]);
            acc[0][1] = fma2(an01.x, ve.y, acc[0][1]);
            acc[1][0] = fma2(an01.y, ve.x, acc[1][0]);
            acc[1][1] = fma2(an01.y, ve.y, acc[1][1]);
            acc[2][0] = fma2(an23.x, ve.x, acc[2][0]);
            acc[2][1] = fma2(an23.x, ve.y, acc[2][1]);
            acc[3][0] = fma2(an23.y, ve.x, acc[3][0]);
            acc[3][1] = fma2(an23.y, ve.y, acc[3][1]);
        }
        __syncthreads();
    }
#pragma unroll
    for (int i = 0; i < 4; i++) {
        float2 e01 = up2(acc[i][0]);
        float2 e23 = up2(acc[i][1]);
        float4 st = make_float4(e01.x, e01.y, e23.x, e23.y);
        float* dst = heads + ((size_t)(b * Qq + qoff + n0 + ty * 4 + i)) * Dd + h * HDe + tx * 4;
        if (accum) {
            float4 old = *(float4*)dst;
            st.x += old.x; st.y += old.y; st.z += old.z; st.w += old.w;
        }
        *(float4*)dst = st;
    }
}

// ============= output GEMM: out[8192,256] = heads @ Wout[256,256] =============
__global__ __launch_bounds__(128) void out_kernel(
    const float* __restrict__ A, const float* __restrict__ Wo,
    float* __restrict__ Out)
{
    __shared__ __align__(16) float Asd[32][DSTR];
    __shared__ __align__(16) float Bs [32][64];
    const int m0 = blockIdx.x * 64;
    const int n0 = blockIdx.y * 64;
    const int tid = threadIdx.x;
    const int tx = tid & 7;
    const int ty = tid >> 3;
    const int fr    = tid >> 1;
    const int khalf = (tid & 1) * 16;
    u64 acc[4][4];
#pragma unroll
    for (int i = 0; i < 4; i++)
#pragma unroll
        for (int j = 0; j < 4; j++) acc[i][j] = 0ull;

    for (int k0 = 0; k0 < Dd; k0 += 32) {
#pragma unroll
        for (int i = 0; i < 4; i++) {
            int kq = khalf + i * 4;
            float4 v = *(const float4*)(A + (size_t)(m0 + fr) * Dd + k0 + kq);
            *(u64*)&Asd[kq + 0][2 * fr] = pk2(v.x, v.x);
            *(u64*)&Asd[kq + 1][2 * fr] = pk2(v.y, v.y);
            *(u64*)&Asd[kq + 2][2 * fr] = pk2(v.z, v.z);
            *(u64*)&Asd[kq + 3][2 * fr] = pk2(v.w, v.w);
        }
#pragma unroll
        for (int i = 0; i < 4; i++) {
            int lin = tid + i * 128;
            int kk = lin >> 4;
            int nq = (lin & 15) << 2;
            *(float4*)&Bs[kk][nq] = *(const float4*)(Wo + (size_t)(k0 + kk) * Dd + n0 + nq);
        }
        __syncthreads();
#pragma unroll
        for (int kk = 0; kk < 32; kk++) {
            ulonglong2 am01 = *(const ulonglong2*)&Asd[kk][ty * 8];
            ulonglong2 am23 = *(const ulonglong2*)&Asd[kk][ty * 8 + 4];
            ulonglong2 bn01 = *(const ulonglong2*)&Bs[kk][tx * 8];
            ulonglong2 bn23 = *(const ulonglong2*)&Bs[kk][tx * 8 + 4];
            acc[0][0] = fma2(am01.x, bn01.x, acc[0][0]);
            acc[0][1] = fma2(am01.x, bn01.y, acc[0][1]);
            acc[0][2] = fma2(am01.x, bn23.x, acc[0][2]);
            acc[0][3] = fma2(am01.x, bn23.y, acc[0][3]);
            acc[1][0] = fma2(am01.y, bn01.x, acc[1][0]);
            acc[1][1] = fma2(am01.y, bn01.y, acc[1][1]);
            acc[1][2] = fma2(am01.y, bn23.x, acc[1][2]);
            acc[1][3] = fma2(am01.y, bn23.y, acc[1][3]);
            acc[2][0] = fma2(am23.x, bn01.x, acc[2][0]);
            acc[2][1] = fma2(am23.x, bn01.y, acc[2][1]);
            acc[2][2] = fma2(am23.x, bn23.x, acc[2][2]);
            acc[2][3] = fma2(am23.x, bn23.y, acc[2][3]);
            acc[3][0] = fma2(am23.y, bn01.x, acc[3][0]);
            acc[3][1] = fma2(am23.y, bn01.y, acc[3][1]);
            acc[3][2] = fma2(am23.y, bn23.x, acc[3][2]);
            acc[3][3] = fma2(am23.y, bn23.y, acc[3][3]);
        }
        __syncthreads();
    }
#pragma unroll
    for (int i = 0; i < 4; i++) {
        float2 p0 = up2(acc[i][0]), p1 = up2(acc[i][1]);
        float2 p2 = up2(acc[i][2]), p3 = up2(acc[i][3]);
        float* row = Out + (size_t)(m0 + ty * 4 + i) * Dd + n0 + tx * 8;
        *(float4*)row       = make_float4(p0.x, p0.y, p1.x, p1.y);
        *(float4*)(row + 4) = make_float4(p2.x, p2.y, p3.x, p3.y);
    }
}

// ---------------- launch ----------------
extern "C" void kernel_launch(void* const* d_in, const int* in_sizes, int n_in,
                              void* d_out, int out_size)
{
    const float* h_fea      = (const float*)d_in[0];
    const float* aux        = (const float*)d_in[1];
    const float* Wq_custom  = (const float*)d_in[2];
    const float* Wq_custom1 = (const float*)d_in[3];
    const float* Wk_custom  = (const float*)d_in[4];
    const float* Wv_custom  = (const float*)d_in[5];
    const float* Wq_charge1 = (const float*)d_in[6];
    const float* Wk_charge  = (const float*)d_in[7];
    const float* Wv_charge  = (const float*)d_in[8];
    const float* W1         = (const float*)d_in[9];
    const float* b1         = (const float*)d_in[10];
    const float* W2         = (const float*)d_in[11];
    const float* b2         = (const float*)d_in[12];
    const float* W_out      = (const float*)d_in[13];
    float* out = (float*)d_out;

    float *Qt1, *Qt, *Kc, *Vc, *Qs, *Ks, *Vs, *P1, *P2, *P3, *heads;
    cudaGetSymbolAddress((void**)&Qt1,   g_Qt1);
    cudaGetSymbolAddress((void**)&Qt,    g_Qt);
    cudaGetSymbolAddress((void**)&Kc,    g_Kc);
    cudaGetSymbolAddress((void**)&Vc,    g_Vc);
    cudaGetSymbolAddress((void**)&Qs,    g_Qs);
    cudaGetSymbolAddress((void**)&Ks,    g_Ks);
    cudaGetSymbolAddress((void**)&Vs,    g_Vs);
    cudaGetSymbolAddress((void**)&P1,    g_P1);
    cudaGetSymbolAddress((void**)&P2,    g_P2);
    cudaGetSymbolAddress((void**)&P3,    g_P3);
    cudaGetSymbolAddress((void**)&heads, g_heads);

    ProjArgs pt;
    pt.W[0] = Wq_custom1; pt.O[0] = Qt1;
    pt.W[1] = Wq_custom;  pt.O[1] = Qt;
    pt.W[2] = Wk_custom;  pt.O[2] = Kc;
    pt.W[3] = Wv_custom;  pt.O[3] = Vc;
    proj_kernel<<<dim3(Bb * Tt / 64, 16), 128>>>(h_fea, pt, Tt, S1c);

    ProjArgs ps;
    ps.W[0] = Wq_charge1; ps.O[0] = Qs;
    ps.W[1] = Wk_charge;  ps.O[1] = Ks;
    ps.W[2] = Wv_charge;  ps.O[2] = Vs;
    ps.W[3] = Wq_charge1; ps.O[3] = Qs;  // unused
    proj_kernel<<<dim3(Bb * S1c / 64, 12), 128>>>(h_fea, ps, S1c, 0);

    qk_kernel<<<dim3(Tt / 64,  Tt / 64,  Hh * Bb), 128>>>(Qt1, Kc, P1, Tt,  Tt);
    qk_kernel<<<dim3(S1c / 64, Tt / 64,  Hh * Bb), 128>>>(Qt,  Ks, P2, Tt,  S1c);
    qk_kernel<<<dim3(Tt / 64,  S1c / 64, Hh * Bb), 128>>>(Qs,  Kc, P3, S1c, Tt);

    fuse_softmax_kernel<448, 2><<<Bb * (Tt / 2),  256>>>(P1, aux, W1, b1, W2, b2, Tt,  S1c, S1c);
    fuse_softmax_kernel<64, 16><<<Bb * (Tt / 16), 256>>>(P2, aux, W1, b1, W2, b2, Tt,  S1c, 0);
    fuse_softmax_kernel<448, 2><<<Bb * (S1c / 2), 256>>>(P3, aux, W1, b1, W2, b2, S1c, 0,   S1c);

    av_kernel<<<dim3(1, Tt / 64,  Hh * Bb), 128>>>(P1, Vc, heads, Tt,  Tt,  S1c, 0);
    av_kernel<<<dim3(1, Tt / 64,  Hh * Bb), 128>>>(P2, Vs, heads, Tt,  S1c, S1c, 1);
    av_kernel<<<dim3(1, S1c / 64, Hh * Bb), 128>>>(P3, Vc, heads, S1c, Tt,  0,   0);

    out_kernel<<<dim3(Bb * Qq / 64, Dd / 64), 128>>>(heads, W_out, out);
}

// round 8
// speedup vs baseline: 1.2905x; 1.2905x over previous
#include <cuda_runtime.h>
#include <cuda_bf16.h>
#include <cstdio>

#define Hh  8
#define Dd  256
#define HDe 32
#define Bb  16
#define Qq  512
#define S1c 64
#define Tt  448

typedef unsigned long long u64;
typedef unsigned int u32;

// ---- packed f32x2 helpers (PTX-only) ----
__device__ __forceinline__ u64 pk2(float x, float y) {
    u64 r; asm("mov.b64 %0, {%1, %2};" : "=l"(r) : "f"(x), "f"(y)); return r;
}
__device__ __forceinline__ float2 up2(u64 v) {
    float2 r; asm("mov.b64 {%0, %1}, %2;" : "=f"(r.x), "=f"(r.y) : "l"(v)); return r;
}
__device__ __forceinline__ u64 fma2(u64 a, u64 b, u64 c) {
    u64 d; asm("fma.rn.f32x2 %0, %1, %2, %3;" : "=l"(d) : "l"(a), "l"(b), "l"(c)); return d;
}

// ---------------- static scratch ----------------
__device__ float g_Qt1[Hh*Bb*Tt*HDe];
__device__ float g_Qt [Hh*Bb*Tt*HDe];
__device__ float g_Kc [Hh*Bb*Tt*HDe];
__device__ float g_Vc [Hh*Bb*Tt*HDe];
__device__ float g_Qs [Hh*Bb*S1c*HDe];
__device__ float g_Ks [Hh*Bb*S1c*HDe];
__device__ float g_Vs [Hh*Bb*S1c*HDe];
__device__ float g_P1 [Hh*Bb*Tt*Tt];
__device__ float g_P2 [Hh*Bb*Tt*S1c];
__device__ float g_P3 [Hh*Bb*S1c*Tt];
__device__ float g_heads[Bb*Qq*Dd];      // [b][q][h][e]

// bf16 hi/lo splits
__device__ __nv_bfloat16 g_Xhi[Bb*Qq*Dd], g_Xlo[Bb*Qq*Dd];       // h_fea split
__device__ __nv_bfloat16 g_Hhi[Bb*Qq*Dd], g_Hlo[Bb*Qq*Dd];       // heads split
__device__ __nv_bfloat16 g_Wbh[8*256*256], g_Wbl[8*256*256];     // B[col][k], 8 sets

// ================= conversion kernels =================
__global__ __launch_bounds__(256) void cvt_split_kernel(
    const float* __restrict__ src, __nv_bfloat16* __restrict__ hi,
    __nv_bfloat16* __restrict__ lo, int n4)
{
    int i = blockIdx.x * 256 + threadIdx.x;
    if (i >= n4) return;
    float4 v = ((const float4*)src)[i];
    __nv_bfloat16 h0 = __float2bfloat16(v.x);
    __nv_bfloat16 h1 = __float2bfloat16(v.y);
    __nv_bfloat16 h2 = __float2bfloat16(v.z);
    __nv_bfloat16 h3 = __float2bfloat16(v.w);
    __nv_bfloat16 l0 = __float2bfloat16(v.x - __bfloat162float(h0));
    __nv_bfloat16 l1 = __float2bfloat16(v.y - __bfloat162float(h1));
    __nv_bfloat16 l2 = __float2bfloat16(v.z - __bfloat162float(h2));
    __nv_bfloat16 l3 = __float2bfloat16(v.w - __bfloat162float(h3));
    ((__nv_bfloat162*)hi)[i*2]   = __nv_bfloat162(h0, h1);
    ((__nv_bfloat162*)hi)[i*2+1] = __nv_bfloat162(h2, h3);
    ((__nv_bfloat162*)lo)[i*2]   = __nv_bfloat162(l0, l1);
    ((__nv_bfloat162*)lo)[i*2+1] = __nv_bfloat162(l2, l3);
}

struct WArgs { const float* W[8]; };

// builds B[col][k] per set: sets 0..6 from W[h][k][e] (col=h*32+e), set 7 = W_out transpose
__global__ __launch_bounds__(256) void cvt_w_kernel(
    WArgs wa, __nv_bfloat16* __restrict__ bh, __nv_bfloat16* __restrict__ bl)
{
    int i = blockIdx.x * 256 + threadIdx.x;   // 8*65536 total
    int s = i >> 16;
    int r = i & 65535;
    int c = r >> 8, k = r & 255;
    const float* W = wa.W[s];
    float x = (s < 7) ? W[(c >> 5) * 8192 + k * 32 + (c & 31)] : W[k * 256 + c];
    __nv_bfloat16 h = __float2bfloat16(x);
    bh[i] = h;
    bl[i] = __float2bfloat16(x - __bfloat162float(h));
}

// ================= HMMA bf16 3-term GEMM =================
// C[128,64] tile = A[128,256] x B[64,256]^T, A/B split hi/lo, 3-term product.
struct HArgs {
    const __nv_bfloat16 *Ahi, *Alo;   // [row][256]
    const __nv_bfloat16 *Bhi, *Blo;   // [col][256] (base incl. set offset)
    float* O[4];
    int TL, qoff, mode;               // mode 0 = proj scatter, 1 = plain row-major
};

#define ASTR 40

__device__ __forceinline__ u32 frag_ld(const __nv_bfloat16* Mb, int rowbase, int G, int lane) {
    int pc = (((G + (rowbase >> 3)) & 3) << 3) + (lane & 3) * 2;
    return *(const u32*)(Mb + (rowbase + (lane >> 2)) * ASTR + pc);
}

__device__ __forceinline__ void mma_bf16(float* d, const u32* a, u32 b0, u32 b1) {
    asm volatile(
        "mma.sync.aligned.m16n8k16.row.col.f32.bf16.bf16.f32 "
        "{%0,%1,%2,%3}, {%4,%5,%6,%7}, {%8,%9}, {%0,%1,%2,%3};"
        : "+f"(d[0]), "+f"(d[1]), "+f"(d[2]), "+f"(d[3])
        : "r"(a[0]), "r"(a[1]), "r"(a[2]), "r"(a[3]), "r"(b0), "r"(b1));
}

__global__ __launch_bounds__(128) void hmma_kernel(HArgs args)
{
    __shared__ __align__(16) __nv_bfloat16 Ah[128][ASTR], Al[128][ASTR];
    __shared__ __align__(16) __nv_bfloat16 Bh[64][ASTR],  Bl[64][ASTR];
    const int m0   = blockIdx.x * 128;
    const int col0 = blockIdx.y * 64;
    const int tid  = threadIdx.x;
    const int warp = tid >> 5, lane = tid & 31;

    float acc[2][8][4];
#pragma unroll
    for (int mf = 0; mf < 2; mf++)
#pragma unroll
        for (int nf = 0; nf < 8; nf++)
#pragma unroll
            for (int j = 0; j < 4; j++) acc[mf][nf][j] = 0.f;

    // A row remap (one row per thread)
    int t = m0 + tid;
    int ab = t / args.TL;
    size_t arow = ((size_t)ab * Qq + args.qoff + (t - ab * args.TL)) * 256;
    // B row
    const int br = tid & 63;
    const __nv_bfloat16* Bsrc = ((tid < 64) ? args.Bhi : args.Blo) + (size_t)(col0 + br) * 256;
    const int rswA = (tid >> 3) & 3;
    const int rswB = (br >> 3) & 3;

    for (int k0 = 0; k0 < 256; k0 += 32) {
        if (k0) __syncthreads();
        const uint4* sAh = (const uint4*)(args.Ahi + arow + k0);
        const uint4* sAl = (const uint4*)(args.Alo + arow + k0);
#pragma unroll
        for (int g = 0; g < 4; g++) {
            int pg = ((g + rswA) & 3) << 3;
            *(uint4*)&Ah[tid][pg] = sAh[g];
            *(uint4*)&Al[tid][pg] = sAl[g];
        }
        {
            const uint4* sB = (const uint4*)(Bsrc + k0);
            __nv_bfloat16 (*Bd)[ASTR] = (tid < 64) ? Bh : Bl;
#pragma unroll
            for (int g = 0; g < 4; g++) {
                int pg = ((g + rswB) & 3) << 3;
                *(uint4*)&Bd[br][pg] = sB[g];
            }
        }
        __syncthreads();
#pragma unroll
        for (int ks = 0; ks < 2; ks++) {
            u32 ah[2][4], al[2][4];
#pragma unroll
            for (int mf = 0; mf < 2; mf++) {
                int rr = warp * 32 + mf * 16;
                ah[mf][0] = frag_ld(&Ah[0][0], rr,     2*ks,   lane);
                ah[mf][1] = frag_ld(&Ah[0][0], rr + 8, 2*ks,   lane);
                ah[mf][2] = frag_ld(&Ah[0][0], rr,     2*ks+1, lane);
                ah[mf][3] = frag_ld(&Ah[0][0], rr + 8, 2*ks+1, lane);
                al[mf][0] = frag_ld(&Al[0][0], rr,     2*ks,   lane);
                al[mf][1] = frag_ld(&Al[0][0], rr + 8, 2*ks,   lane);
                al[mf][2] = frag_ld(&Al[0][0], rr,     2*ks+1, lane);
                al[mf][3] = frag_ld(&Al[0][0], rr + 8, 2*ks+1, lane);
            }
#pragma unroll
            for (int nf = 0; nf < 8; nf++) {
                int nr = nf * 8;
                u32 bh0 = frag_ld(&Bh[0][0], nr, 2*ks,   lane);
                u32 bh1 = frag_ld(&Bh[0][0], nr, 2*ks+1, lane);
                u32 bl0 = frag_ld(&Bl[0][0], nr, 2*ks,   lane);
                u32 bl1 = frag_ld(&Bl[0][0], nr, 2*ks+1, lane);
#pragma unroll
                for (int mf = 0; mf < 2; mf++) {
                    mma_bf16(acc[mf][nf], ah[mf], bh0, bh1);
                    mma_bf16(acc[mf][nf], ah[mf], bl0, bl1);
                    mma_bf16(acc[mf][nf], al[mf], bh0, bh1);
                }
            }
        }
    }

    // epilogue
#pragma unroll
    for (int mf = 0; mf < 2; mf++) {
#pragma unroll
        for (int nf = 0; nf < 8; nf++) {
            int lc = nf * 8 + (lane & 3) * 2;
            int t0 = m0 + warp * 32 + mf * 16 + (lane >> 2);
            int t1 = t0 + 8;
            float2 v0 = make_float2(acc[mf][nf][0], acc[mf][nf][1]);
            float2 v1 = make_float2(acc[mf][nf][2], acc[mf][nf][3]);
            if (args.mode == 0) {
                int c = (blockIdx.y & 3) * 64 + lc;
                int h = c >> 5, e = c & 31;
                float* O = args.O[blockIdx.y >> 2];
                int b0i = t0 / args.TL, n0i = t0 - b0i * args.TL;
                int b1i = t1 / args.TL, n1i = t1 - b1i * args.TL;
                *(float2*)(O + (((size_t)h * Bb + b0i) * args.TL + n0i) * HDe + e) = v0;
                *(float2*)(O + (((size_t)h * Bb + b1i) * args.TL + n1i) * HDe + e) = v1;
            } else {
                int d = blockIdx.y * 64 + lc;
                float* O = args.O[0];
                *(float2*)(O + (size_t)t0 * 256 + d) = v0;
                *(float2*)(O + (size_t)t1 * 256 + d) = v1;
            }
        }
    }
}

// ================= batched QK^T (R4, best known) =================
__global__ __launch_bounds__(256) void qk_kernel(
    const float* __restrict__ Qm, const float* __restrict__ Km,
    float* __restrict__ S, int Nq, int Nk)
{
    __shared__ __align__(16) float Qs[32][64];
    __shared__ __align__(16) float Ks[32][64];
    const int z = blockIdx.z;
    const float* Qb = Qm + (size_t)z * Nq * HDe;
    const float* Kb = Km + (size_t)z * Nk * HDe;
    float* Sb = S + (size_t)z * Nq * Nk;
    const int mq0 = blockIdx.y * 64;
    const int mk0 = blockIdx.x * 64;
    const int tid = threadIdx.x;
#pragma unroll
    for (int i = 0; i < 2; i++) {
        int lin = tid + i * 256;
        int r = lin >> 3;
        int eq = (lin & 7) << 2;
        float4 v = *(const float4*)(Qb + (size_t)(mq0 + r) * HDe + eq);
        Qs[eq + 0][r] = v.x; Qs[eq + 1][r] = v.y;
        Qs[eq + 2][r] = v.z; Qs[eq + 3][r] = v.w;
        float4 w = *(const float4*)(Kb + (size_t)(mk0 + r) * HDe + eq);
        Ks[eq + 0][r] = w.x; Ks[eq + 1][r] = w.y;
        Ks[eq + 2][r] = w.z; Ks[eq + 3][r] = w.w;
    }
    __syncthreads();
    const int tx = tid & 15, ty = tid >> 4;
    u64 acc2[4][2];
#pragma unroll
    for (int i = 0; i < 4; i++) { acc2[i][0] = 0ull; acc2[i][1] = 0ull; }
#pragma unroll
    for (int e = 0; e < 32; e++) {
        float4 a = *(const float4*)&Qs[e][ty << 2];
        ulonglong2 bq = *(const ulonglong2*)&Ks[e][tx << 2];
        u64 a0 = pk2(a.x, a.x), a1 = pk2(a.y, a.y);
        u64 a2 = pk2(a.z, a.z), a3 = pk2(a.w, a.w);
        acc2[0][0] = fma2(a0, bq.x, acc2[0][0]); acc2[0][1] = fma2(a0, bq.y, acc2[0][1]);
        acc2[1][0] = fma2(a1, bq.x, acc2[1][0]); acc2[1][1] = fma2(a1, bq.y, acc2[1][1]);
        acc2[2][0] = fma2(a2, bq.x, acc2[2][0]); acc2[2][1] = fma2(a2, bq.y, acc2[2][1]);
        acc2[3][0] = fma2(a3, bq.x, acc2[3][0]); acc2[3][1] = fma2(a3, bq.y, acc2[3][1]);
    }
#pragma unroll
    for (int i = 0; i < 4; i++) {
        ulonglong2 st; st.x = acc2[i][0]; st.y = acc2[i][1];
        *(ulonglong2*)(Sb + (size_t)(mq0 + (ty << 2) + i) * Nk + mk0 + (tx << 2)) = st;
    }
}

// ================= fuse MLP + softmax (R4, best known) =================
template<int NK, int QPB>
__global__ __launch_bounds__(256) void fuse_softmax_kernel(
    float* __restrict__ S, const float* __restrict__ aux,
    const float* __restrict__ W1, const float* __restrict__ b1,
    const float* __restrict__ W2, const float* __restrict__ b2,
    int Nq, int qn_off, int qm_off)
{
    __shared__ __align__(16) u64 sW1d[16][16];
    __shared__ __align__(16) u64 sW2d[16][8];
    __shared__ u64 sb1d[16], sb2d[8];
    __shared__ __align__(16) float fs[QPB][8][NK];
    const int tid = threadIdx.x;
    { int j = tid >> 4, c = tid & 15; float w = W1[c * 16 + j]; sW1d[j][c] = pk2(w, w); }
    if (tid < 128) { int j = tid >> 3, h = tid & 7; float w = W2[j * 8 + h]; sW2d[j][h] = pk2(w, w); }
    if (tid < 16)  { float w = b1[tid]; sb1d[tid] = pk2(w, w); }
    if (tid < 8)   { float w = b2[tid]; sb2d[tid] = pk2(w, w); }
    __syncthreads();

    const int nblocks = Nq / QPB;
    const int nb = blockIdx.x % nblocks;
    const int b  = blockIdx.x / nblocks;
    constexpr int TPQ = 256 / QPB;
    const int ql = tid / TPQ;
    const int tl = tid % TPQ;
    const int n  = nb * QPB + ql;
    const int m0 = tl * 4;

    if (m0 < NK) {
        u64 x2[16][2];
#pragma unroll
        for (int h = 0; h < 8; h++) {
            ulonglong2 v = *(const ulonglong2*)(S + ((size_t)(h * Bb + b) * Nq + n) * NK + m0);
            x2[h][0] = v.x; x2[h][1] = v.y;
            ulonglong2 w = *(const ulonglong2*)(aux + ((size_t)(h * Bb + b) * Qq + qn_off + n) * Qq + qm_off + m0);
            x2[8 + h][0] = w.x; x2[8 + h][1] = w.y;
        }
        u64 f0[8], f1[8];
#pragma unroll
        for (int h = 0; h < 8; h++) { f0[h] = sb2d[h]; f1[h] = f0[h]; }
#pragma unroll
        for (int j = 0; j < 16; j++) {
            u64 h0 = sb1d[j], h1 = h0;
            ulonglong2 w1p[8];
#pragma unroll
            for (int p = 0; p < 8; p++) w1p[p] = *(const ulonglong2*)&sW1d[j][p * 2];
#pragma unroll
            for (int c = 0; c < 16; c++) {
                u64 wv = (c & 1) ? w1p[c >> 1].y : w1p[c >> 1].x;
                h0 = fma2(x2[c][0], wv, h0);
                h1 = fma2(x2[c][1], wv, h1);
            }
            float2 ra = up2(h0), rb = up2(h1);
            ra.x = fmaxf(ra.x, 0.f); ra.y = fmaxf(ra.y, 0.f);
            rb.x = fmaxf(rb.x, 0.f); rb.y = fmaxf(rb.y, 0.f);
            u64 r0 = pk2(ra.x, ra.y), r1 = pk2(rb.x, rb.y);
            ulonglong2 w2p[4];
#pragma unroll
            for (int p = 0; p < 4; p++) w2p[p] = *(const ulonglong2*)&sW2d[j][p * 2];
#pragma unroll
            for (int h = 0; h < 8; h++) {
                u64 wv = (h & 1) ? w2p[h >> 1].y : w2p[h >> 1].x;
                f0[h] = fma2(r0, wv, f0[h]);
                f1[h] = fma2(r1, wv, f1[h]);
            }
        }
#pragma unroll
        for (int h = 0; h < 8; h++) {
            ulonglong2 st; st.x = f0[h]; st.y = f1[h];
            *(ulonglong2*)&fs[ql][h][m0] = st;
        }
    }
    __syncthreads();

    const int warp = tid >> 5, lane = tid & 31;
    constexpr int R = QPB * 8;
    for (int row = warp; row < R; row += 8) {
        int qr = row >> 3;
        int hr = row & 7;
        float* frow = fs[qr][hr];
        float mx = -3.0e38f;
        for (int m = lane; m < NK; m += 32) mx = fmaxf(mx, frow[m]);
#pragma unroll
        for (int o = 16; o > 0; o >>= 1) mx = fmaxf(mx, __shfl_xor_sync(0xffffffffu, mx, o));
        float sum = 0.f;
        for (int m = lane; m < NK; m += 32) {
            float ev = __expf(frow[m] - mx);
            frow[m] = ev;
            sum += ev;
        }
#pragma unroll
        for (int o = 16; o > 0; o >>= 1) sum += __shfl_xor_sync(0xffffffffu, sum, o);
        float inv = 1.f / sum;
        float* Srow = S + ((size_t)(hr * Bb + b) * Nq + nb * QPB + qr) * NK;
        for (int m = lane; m < NK; m += 32) Srow[m] = frow[m] * inv;
    }
}

// ================= batched AV (R4, best known) =================
__global__ __launch_bounds__(256) void av_kernel(
    const float* __restrict__ P, const float* __restrict__ V,
    float* __restrict__ heads, int Nq, int Nk, int qoff, int accum)
{
    __shared__ __align__(16) float As[32][64];
    __shared__ __align__(16) float Bs[32][HDe];
    const int z = blockIdx.z;
    const int h = z >> 4, b = z & 15;
    const float* Pb = P + (size_t)z * Nq * Nk;
    const float* Vb = V + (size_t)z * Nk * HDe;
    const int n0 = blockIdx.y * 64;
    const int tid = threadIdx.x;
    const int e = tid & 31;
    const int rg = tid >> 5;
    u64 acc2[4];
#pragma unroll
    for (int i = 0; i < 4; i++) acc2[i] = 0ull;

    for (int k0 = 0; k0 < Nk; k0 += 32) {
#pragma unroll
        for (int i = 0; i < 2; i++) {
            int lin = tid + i * 256;
            int r = lin >> 3;
            int mq = (lin & 7) << 2;
            float4 v = *(const float4*)(Pb + (size_t)(n0 + r) * Nk + k0 + mq);
            As[mq + 0][r] = v.x; As[mq + 1][r] = v.y;
            As[mq + 2][r] = v.z; As[mq + 3][r] = v.w;
        }
        {
            int kk = tid >> 3;
            int eq = (tid & 7) << 2;
            *(float4*)&Bs[kk][eq] = *(const float4*)(Vb + (size_t)(k0 + kk) * HDe + eq);
        }
        __syncthreads();
#pragma unroll
        for (int kk = 0; kk < 32; kk++) {
            float bv = Bs[kk][e];
            u64 bd = pk2(bv, bv);
            ulonglong2 aa = *(const ulonglong2*)&As[kk][rg * 8];
            ulonglong2 ab = *(const ulonglong2*)&As[kk][rg * 8 + 4];
            acc2[0] = fma2(aa.x, bd, acc2[0]);
            acc2[1] = fma2(aa.y, bd, acc2[1]);
            acc2[2] = fma2(ab.x, bd, acc2[2]);
            acc2[3] = fma2(ab.y, bd, acc2[3]);
        }
        __syncthreads();
    }
#pragma unroll
    for (int p = 0; p < 4; p++) {
        float2 v = up2(acc2[p]);
        int n = n0 + rg * 8 + p * 2;
        size_t a0 = ((size_t)(b * Qq + qoff + n)) * Dd + h * HDe + e;
        size_t a1 = a0 + Dd;
        if (accum) { heads[a0] += v.x; heads[a1] += v.y; }
        else       { heads[a0] = v.x;  heads[a1] = v.y; }
    }
}

// ---------------- launch ----------------
extern "C" void kernel_launch(void* const* d_in, const int* in_sizes, int n_in,
                              void* d_out, int out_size)
{
    const float* h_fea      = (const float*)d_in[0];
    const float* aux        = (const float*)d_in[1];
    const float* Wq_custom  = (const float*)d_in[2];
    const float* Wq_custom1 = (const float*)d_in[3];
    const float* Wk_custom  = (const float*)d_in[4];
    const float* Wv_custom  = (const float*)d_in[5];
    const float* Wq_charge1 = (const float*)d_in[6];
    const float* Wk_charge  = (const float*)d_in[7];
    const float* Wv_charge  = (const float*)d_in[8];
    const float* W1         = (const float*)d_in[9];
    const float* b1         = (const float*)d_in[10];
    const float* W2         = (const float*)d_in[11];
    const float* b2         = (const float*)d_in[12];
    const float* W_out      = (const float*)d_in[13];
    float* out = (float*)d_out;

    float *Qt1, *Qt, *Kc, *Vc, *Qs, *Ks, *Vs, *P1, *P2, *P3, *heads;
    __nv_bfloat16 *Xhi, *Xlo, *Hhi, *Hlo, *Wbh, *Wbl;
    cudaGetSymbolAddress((void**)&Qt1,   g_Qt1);
    cudaGetSymbolAddress((void**)&Qt,    g_Qt);
    cudaGetSymbolAddress((void**)&Kc,    g_Kc);
    cudaGetSymbolAddress((void**)&Vc,    g_Vc);
    cudaGetSymbolAddress((void**)&Qs,    g_Qs);
    cudaGetSymbolAddress((void**)&Ks,    g_Ks);
    cudaGetSymbolAddress((void**)&Vs,    g_Vs);
    cudaGetSymbolAddress((void**)&P1,    g_P1);
    cudaGetSymbolAddress((void**)&P2,    g_P2);
    cudaGetSymbolAddress((void**)&P3,    g_P3);
    cudaGetSymbolAddress((void**)&heads, g_heads);
    cudaGetSymbolAddress((void**)&Xhi,   g_Xhi);
    cudaGetSymbolAddress((void**)&Xlo,   g_Xlo);
    cudaGetSymbolAddress((void**)&Hhi,   g_Hhi);
    cudaGetSymbolAddress((void**)&Hlo,   g_Hlo);
    cudaGetSymbolAddress((void**)&Wbh,   g_Wbh);
    cudaGetSymbolAddress((void**)&Wbl,   g_Wbl);

    // 1. splits
    cvt_split_kernel<<<(Bb*Qq*Dd/4 + 255)/256, 256>>>(h_fea, Xhi, Xlo, Bb*Qq*Dd/4);
    WArgs wa;
    wa.W[0] = Wq_custom1; wa.W[1] = Wq_custom; wa.W[2] = Wk_custom; wa.W[3] = Wv_custom;
    wa.W[4] = Wq_charge1; wa.W[5] = Wk_charge; wa.W[6] = Wv_charge; wa.W[7] = W_out;
    cvt_w_kernel<<<8*256*256/256, 256>>>(wa, Wbh, Wbl);

    // 2. projections via HMMA
    HArgs ht;
    ht.Ahi = Xhi; ht.Alo = Xlo; ht.Bhi = Wbh; ht.Blo = Wbl;
    ht.O[0] = Qt1; ht.O[1] = Qt; ht.O[2] = Kc; ht.O[3] = Vc;
    ht.TL = Tt; ht.qoff = S1c; ht.mode = 0;
    hmma_kernel<<<dim3(Bb*Tt/128, 16), 128>>>(ht);

    HArgs hs;
    hs.Ahi = Xhi; hs.Alo = Xlo; hs.Bhi = Wbh + 4*65536; hs.Blo = Wbl + 4*65536;
    hs.O[0] = Qs; hs.O[1] = Ks; hs.O[2] = Vs; hs.O[3] = Qs;
    hs.TL = S1c; hs.qoff = 0; hs.mode = 0;
    hmma_kernel<<<dim3(Bb*S1c/128, 12), 128>>>(hs);

    // 3. QK^T
    qk_kernel<<<dim3(Tt / 64,  Tt / 64,  Hh * Bb), 256>>>(Qt1, Kc, P1, Tt,  Tt);
    qk_kernel<<<dim3(S1c / 64, Tt / 64,  Hh * Bb), 256>>>(Qt,  Ks, P2, Tt,  S1c);
    qk_kernel<<<dim3(Tt / 64,  S1c / 64, Hh * Bb), 256>>>(Qs,  Kc, P3, S1c, Tt);

    // 4. fuse MLP + softmax
    fuse_softmax_kernel<448, 2><<<Bb * (Tt / 2),  256>>>(P1, aux, W1, b1, W2, b2, Tt,  S1c, S1c);
    fuse_softmax_kernel<64, 16><<<Bb * (Tt / 16), 256>>>(P2, aux, W1, b1, W2, b2, Tt,  S1c, 0);
    fuse_softmax_kernel<448, 2><<<Bb * (S1c / 2), 256>>>(P3, aux, W1, b1, W2, b2, S1c, 0,   S1c);

    // 5. AV
    av_kernel<<<dim3(1, Tt / 64,  Hh * Bb), 256>>>(P1, Vc, heads, Tt,  Tt,  S1c, 0);
    av_kernel<<<dim3(1, Tt / 64,  Hh * Bb), 256>>>(P2, Vs, heads, Tt,  S1c, S1c, 1);
    av_kernel<<<dim3(1, S1c / 64, Hh * Bb), 256>>>(P3, Vc, heads, S1c, Tt,  0,   0);

    // 6. split heads, output GEMM via HMMA
    cvt_split_kernel<<<(Bb*Qq*Dd/4 + 255)/256, 256>>>(heads, Hhi, Hlo, Bb*Qq*Dd/4);
    HArgs ho;
    ho.Ahi = Hhi; ho.Alo = Hlo; ho.Bhi = Wbh + 7*65536; ho.Blo = Wbl + 7*65536;
    ho.O[0] = out; ho.O[1] = out; ho.O[2] = out; ho.O[3] = out;
    ho.TL = Qq; ho.qoff = 0; ho.mode = 1;
    hmma_kernel<<<dim3(Bb*Qq/128, 4), 128>>>(ho);
}

// round 9
// speedup vs baseline: 1.4909x; 1.1553x over previous
#include <cuda_runtime.h>
#include <cuda_bf16.h>

#define Hh  8
#define Dd  256
#define HDe 32
#define Bb  16
#define Qq  512
#define S1c 64
#define Tt  448

typedef unsigned long long u64;
typedef unsigned int u32;
typedef __nv_bfloat16  bf16;
typedef __nv_bfloat162 bf162;

// ---- packed f32x2 helpers (fuse kernel) ----
__device__ __forceinline__ u64 pk2(float x, float y) {
    u64 r; asm("mov.b64 %0, {%1, %2};" : "=l"(r) : "f"(x), "f"(y)); return r;
}
__device__ __forceinline__ float2 up2(u64 v) {
    float2 r; asm("mov.b64 {%0, %1}, %2;" : "=f"(r.x), "=f"(r.y) : "l"(v)); return r;
}
__device__ __forceinline__ u64 fma2(u64 a, u64 b, u64 c) {
    u64 d; asm("fma.rn.f32x2 %0, %1, %2, %3;" : "=l"(d) : "l"(a), "l"(b), "l"(c)); return d;
}

// ---------------- static scratch ----------------
__device__ float g_P1[128*Tt*Tt];
__device__ float g_P2[128*Tt*S1c];
__device__ float g_P3[128*S1c*Tt];
__device__ float g_heads[Bb*Qq*Dd];

__device__ bf16 g_Xhi[Bb*Qq*Dd], g_Xlo[Bb*Qq*Dd];
__device__ bf16 g_Hhi[Bb*Qq*Dd], g_Hlo[Bb*Qq*Dd];
__device__ bf16 g_Wbh[8*256*256], g_Wbl[8*256*256];

// proj bf16 splits, layout [(h*16+b)*TL + n]*32 + e
__device__ bf16 g_Q1h[128*Tt*32],  g_Q1l[128*Tt*32];    // set0 Qt1
__device__ bf16 g_Q0h[128*Tt*32],  g_Q0l[128*Tt*32];    // set1 Qt
__device__ bf16 g_Kch[128*Tt*32],  g_Kcl[128*Tt*32];    // set2 Kc
__device__ bf16 g_Vch[128*Tt*32],  g_Vcl[128*Tt*32];    // set3 Vc
__device__ bf16 g_Qsh[128*S1c*32], g_Qsl[128*S1c*32];   // set4 Qs
__device__ bf16 g_Ksh[128*S1c*32], g_Ksl[128*S1c*32];   // set5 Ks
__device__ bf16 g_Vsh[128*S1c*32], g_Vsl[128*S1c*32];   // set6 Vs

// V transposed: [(z*32 + e)*TL + t]
__device__ bf16 g_Vtch[128*32*Tt],  g_Vtcl[128*32*Tt];
__device__ bf16 g_Vtsh[128*32*S1c], g_Vtsl[128*32*S1c];

// probabilities bf16 splits, layout [(z*Nq + n)*Nk + m]
__device__ bf16 g_P1h[128*Tt*Tt],  g_P1l[128*Tt*Tt];
__device__ bf16 g_P2h[128*Tt*S1c], g_P2l[128*Tt*S1c];
__device__ bf16 g_P3h[128*S1c*Tt], g_P3l[128*S1c*Tt];

// ================= conversion kernels =================
__global__ __launch_bounds__(256) void cvt_split_kernel(
    const float* __restrict__ src, bf16* __restrict__ hi,
    bf16* __restrict__ lo, int n4)
{
    int i = blockIdx.x * 256 + threadIdx.x;
    if (i >= n4) return;
    float4 v = ((const float4*)src)[i];
    bf16 h0 = __float2bfloat16(v.x), h1 = __float2bfloat16(v.y);
    bf16 h2 = __float2bfloat16(v.z), h3 = __float2bfloat16(v.w);
    ((bf162*)hi)[i*2]   = bf162(h0, h1);
    ((bf162*)hi)[i*2+1] = bf162(h2, h3);
    ((bf162*)lo)[i*2]   = bf162(__float2bfloat16(v.x - __bfloat162float(h0)),
                                __float2bfloat16(v.y - __bfloat162float(h1)));
    ((bf162*)lo)[i*2+1] = bf162(__float2bfloat16(v.z - __bfloat162float(h2)),
                                __float2bfloat16(v.w - __bfloat162float(h3)));
}

struct WArgs { const float* W[8]; };

__global__ __launch_bounds__(256) void cvt_w_kernel(
    WArgs wa, bf16* __restrict__ bh, bf16* __restrict__ bl)
{
    int i = blockIdx.x * 256 + threadIdx.x;
    int s = i >> 16;
    int r = i & 65535;
    int c = r >> 8, k = r & 255;
    const float* W = wa.W[s];
    float x = (s < 7) ? W[(c >> 5) * 8192 + k * 32 + (c & 31)] : W[k * 256 + c];
    bf16 h = __float2bfloat16(x);
    bh[i] = h;
    bl[i] = __float2bfloat16(x - __bfloat162float(h));
}

// ================= shared HMMA machinery =================
#define ASTR 40

__device__ __forceinline__ u32 frag_ld(const bf16* Mb, int rowbase, int G, int lane) {
    int pc = (((G + (rowbase >> 3)) & 3) << 3) + (lane & 3) * 2;
    return *(const u32*)(Mb + (rowbase + (lane >> 2)) * ASTR + pc);
}

__device__ __forceinline__ void mma_bf16(float* d, const u32* a, u32 b0, u32 b1) {
    asm volatile(
        "mma.sync.aligned.m16n8k16.row.col.f32.bf16.bf16.f32 "
        "{%0,%1,%2,%3}, {%4,%5,%6,%7}, {%8,%9}, {%0,%1,%2,%3};"
        : "+f"(d[0]), "+f"(d[1]), "+f"(d[2]), "+f"(d[3])
        : "r"(a[0]), "r"(a[1]), "r"(a[2]), "r"(a[3]), "r"(b0), "r"(b1));
}

__device__ __forceinline__ void split_st(bf16* hp, bf16* lp, size_t idx, float2 v) {
    bf16 h0 = __float2bfloat16(v.x), h1 = __float2bfloat16(v.y);
    *(bf162*)(hp + idx) = bf162(h0, h1);
    *(bf162*)(lp + idx) = bf162(__float2bfloat16(v.x - __bfloat162float(h0)),
                                __float2bfloat16(v.y - __bfloat162float(h1)));
}

// ================= proj/out HMMA kernel =================
struct HArgs {
    const bf16 *Ahi, *Alo;       // [row][256]
    const bf16 *Bh, *Bl;         // all 8 sets, [set][col][k]
    float* Ofp;                  // mode 1 output
    bf16 *Oh[7], *Ol[7];         // mode 0 split outputs per set
    int mode;                    // 0 = merged proj, 1 = out GEMM
};

__global__ __launch_bounds__(128) void hmma_kernel(HArgs args)
{
    __shared__ __align__(16) bf16 Ah[128][ASTR], Al[128][ASTR];
    __shared__ __align__(16) bf16 Bhs[64][ASTR], Bls[64][ASTR];
    const int x = blockIdx.x, y = blockIdx.y;
    int set, col0, TL, qoff, m0;
    if (args.mode == 0) {
        if (x < 56) { set = y >> 2; col0 = (y & 3) * 64; TL = Tt; qoff = S1c; m0 = x * 128; }
        else {
            if (y >= 12) return;
            set = 4 + (y >> 2); col0 = (y & 3) * 64; TL = S1c; qoff = 0; m0 = (x - 56) * 128;
        }
    } else { set = 7; col0 = y * 64; TL = Qq; qoff = 0; m0 = x * 128; }

    const int tid = threadIdx.x;
    const int warp = tid >> 5, lane = tid & 31;

    float acc[2][8][4];
#pragma unroll
    for (int mf = 0; mf < 2; mf++)
#pragma unroll
        for (int nf = 0; nf < 8; nf++)
#pragma unroll
            for (int j = 0; j < 4; j++) acc[mf][nf][j] = 0.f;

    int t = m0 + tid;
    int ab = t / TL;
    size_t arow = ((size_t)ab * Qq + qoff + (t - ab * TL)) * 256;
    const int br = tid & 63;
    const bf16* Bsrc = ((tid < 64) ? args.Bh : args.Bl) + (size_t)set * 65536 + (size_t)(col0 + br) * 256;
    const int rswA = (tid >> 3) & 3;
    const int rswB = (br >> 3) & 3;

    for (int k0 = 0; k0 < 256; k0 += 32) {
        if (k0) __syncthreads();
        const uint4* sAh = (const uint4*)(args.Ahi + arow + k0);
        const uint4* sAl = (const uint4*)(args.Alo + arow + k0);
#pragma unroll
        for (int g = 0; g < 4; g++) {
            int pg = ((g + rswA) & 3) << 3;
            *(uint4*)&Ah[tid][pg] = sAh[g];
            *(uint4*)&Al[tid][pg] = sAl[g];
        }
        {
            const uint4* sB = (const uint4*)(Bsrc + k0);
            bf16 (*Bd)[ASTR] = (tid < 64) ? Bhs : Bls;
#pragma unroll
            for (int g = 0; g < 4; g++) {
                int pg = ((g + rswB) & 3) << 3;
                *(uint4*)&Bd[br][pg] = sB[g];
            }
        }
        __syncthreads();
#pragma unroll
        for (int ks = 0; ks < 2; ks++) {
            u32 ah[2][4], al[2][4];
#pragma unroll
            for (int mf = 0; mf < 2; mf++) {
                int rr = warp * 32 + mf * 16;
                ah[mf][0] = frag_ld(&Ah[0][0], rr,     2*ks,   lane);
                ah[mf][1] = frag_ld(&Ah[0][0], rr + 8, 2*ks,   lane);
                ah[mf][2] = frag_ld(&Ah[0][0], rr,     2*ks+1, lane);
                ah[mf][3] = frag_ld(&Ah[0][0], rr + 8, 2*ks+1, lane);
                al[mf][0] = frag_ld(&Al[0][0], rr,     2*ks,   lane);
                al[mf][1] = frag_ld(&Al[0][0], rr + 8, 2*ks,   lane);
                al[mf][2] = frag_ld(&Al[0][0], rr,     2*ks+1, lane);
                al[mf][3] = frag_ld(&Al[0][0], rr + 8, 2*ks+1, lane);
            }
#pragma unroll
            for (int nf = 0; nf < 8; nf++) {
                int nr = nf * 8;
                u32 bh0 = frag_ld(&Bhs[0][0], nr, 2*ks,   lane);
                u32 bh1 = frag_ld(&Bhs[0][0], nr, 2*ks+1, lane);
                u32 bl0 = frag_ld(&Bls[0][0], nr, 2*ks,   lane);
                u32 bl1 = frag_ld(&Bls[0][0], nr, 2*ks+1, lane);
#pragma unroll
                for (int mf = 0; mf < 2; mf++) {
                    mma_bf16(acc[mf][nf], ah[mf], bh0, bh1);
                    mma_bf16(acc[mf][nf], ah[mf], bl0, bl1);
                    mma_bf16(acc[mf][nf], al[mf], bh0, bh1);
                }
            }
        }
    }

#pragma unroll
    for (int mf = 0; mf < 2; mf++) {
#pragma unroll
        for (int nf = 0; nf < 8; nf++) {
            int lc = nf * 8 + (lane & 3) * 2;
            int t0 = m0 + warp * 32 + mf * 16 + (lane >> 2);
            int t1 = t0 + 8;
            float2 v0 = make_float2(acc[mf][nf][0], acc[mf][nf][1]);
            float2 v1 = make_float2(acc[mf][nf][2], acc[mf][nf][3]);
            if (args.mode == 0) {
                int c = col0 + lc;
                int h = c >> 5, e = c & 31;
                int b0i = t0 / TL, n0i = t0 - b0i * TL;
                int b1i = t1 / TL, n1i = t1 - b1i * TL;
                size_t i0 = (((size_t)h * Bb + b0i) * TL + n0i) * 32 + e;
                size_t i1 = (((size_t)h * Bb + b1i) * TL + n1i) * 32 + e;
                split_st(args.Oh[set], args.Ol[set], i0, v0);
                split_st(args.Oh[set], args.Ol[set], i1, v1);
            } else {
                int d = col0 + lc;
                *(float2*)(args.Ofp + (size_t)t0 * 256 + d) = v0;
                *(float2*)(args.Ofp + (size_t)t1 * 256 + d) = v1;
            }
        }
    }
}

// ================= V transpose: [t][e] bf16 -> [e][t] bf16 =================
struct VtArgs {
    const bf16 *srcH[2], *srcL[2];
    bf16 *dstH[2], *dstL[2];
    int TL[2];
};
__global__ __launch_bounds__(256) void vt_kernel(VtArgs a)
{
    __shared__ bf16 ts[32][40];
    int bid = blockIdx.x;
    int sel = (bid >= 1792);
    int r = sel ? (bid - 1792) : bid;
    int nt = sel ? 2 : 14;
    int z = r / nt, tc = r % nt;
    int TL = a.TL[sel];
    const int tid = threadIdx.x;
    for (int p = 0; p < 2; p++) {
        const bf16* src = p ? a.srcL[sel] : a.srcH[sel];
        bf16* dst = p ? a.dstL[sel] : a.dstH[sel];
        {
            int tt = tid >> 3, e0 = (tid & 7) * 4;
            *(u64*)&ts[tt][e0] = *(const u64*)(src + ((size_t)z * TL + tc * 32 + tt) * 32 + e0);
        }
        __syncthreads();
        {
            int e = tid >> 3, t0 = (tid & 7) * 4;
            u64 v;
            bf16* pv = (bf16*)&v;
            pv[0] = ts[t0 + 0][e]; pv[1] = ts[t0 + 1][e];
            pv[2] = ts[t0 + 2][e]; pv[3] = ts[t0 + 3][e];
            *(u64*)(dst + ((size_t)z * 32 + e) * TL + tc * 32 + t0) = v;
        }
        __syncthreads();
    }
}

// ================= QK^T HMMA (3 jobs in one launch) =================
struct QKArgs {
    const bf16 *Q1h, *Q1l, *Q0h, *Q0l, *Qsh, *Qsl;
    const bf16 *Kch, *Kcl, *Ksh, *Ksl;
    float *P1, *P2, *P3;
};
__global__ __launch_bounds__(128) void qk_hmma(QKArgs a)
{
    __shared__ __align__(16) bf16 Qhs[64][ASTR], Qls[64][ASTR];
    __shared__ __align__(16) bf16 Khs[64][ASTR], Kls[64][ASTR];
    const int x = blockIdx.x, z = blockIdx.y;
    const bf16 *Qh, *Ql, *Kh, *Kl;
    float* Sb;
    int Nq, Nk, mq0, mk0;
    if (x < 49) {
        Qh = a.Q1h; Ql = a.Q1l; Kh = a.Kch; Kl = a.Kcl;
        Sb = a.P1 + (size_t)z * Tt * Tt; Nq = Tt; Nk = Tt;
        mq0 = (x / 7) * 64; mk0 = (x % 7) * 64;
    } else if (x < 56) {
        Qh = a.Q0h; Ql = a.Q0l; Kh = a.Ksh; Kl = a.Ksl;
        Sb = a.P2 + (size_t)z * Tt * S1c; Nq = Tt; Nk = S1c;
        mq0 = (x - 49) * 64; mk0 = 0;
    } else {
        Qh = a.Qsh; Ql = a.Qsl; Kh = a.Kch; Kl = a.Kcl;
        Sb = a.P3 + (size_t)z * S1c * Tt; Nq = S1c; Nk = Tt;
        mq0 = 0; mk0 = (x - 56) * 64;
    }
    const int tid = threadIdx.x;
    const int warp = tid >> 5, lane = tid & 31;
    {
        int rr = tid & 63;
        int sel = tid >> 6;
        int rsw = (rr >> 3) & 3;
        const uint4* qs = (const uint4*)((sel ? Ql : Qh) + ((size_t)z * Nq + mq0 + rr) * 32);
        const uint4* ks = (const uint4*)((sel ? Kl : Kh) + ((size_t)z * Nk + mk0 + rr) * 32);
        bf16 (*Qd)[ASTR] = sel ? Qls : Qhs;
        bf16 (*Kd)[ASTR] = sel ? Kls : Khs;
#pragma unroll
        for (int g = 0; g < 4; g++) {
            int pg = ((g + rsw) & 3) << 3;
            *(uint4*)&Qd[rr][pg] = qs[g];
            *(uint4*)&Kd[rr][pg] = ks[g];
        }
    }
    __syncthreads();

    float acc[8][4];
#pragma unroll
    for (int nf = 0; nf < 8; nf++)
#pragma unroll
        for (int j = 0; j < 4; j++) acc[nf][j] = 0.f;

    const int rr = warp * 16;
#pragma unroll
    for (int ks = 0; ks < 2; ks++) {
        u32 ah[4], al[4];
        ah[0] = frag_ld(&Qhs[0][0], rr,     2*ks,   lane);
        ah[1] = frag_ld(&Qhs[0][0], rr + 8, 2*ks,   lane);
        ah[2] = frag_ld(&Qhs[0][0], rr,     2*ks+1, lane);
        ah[3] = frag_ld(&Qhs[0][0], rr + 8, 2*ks+1, lane);
        al[0] = frag_ld(&Qls[0][0], rr,     2*ks,   lane);
        al[1] = frag_ld(&Qls[0][0], rr + 8, 2*ks,   lane);
        al[2] = frag_ld(&Qls[0][0], rr,     2*ks+1, lane);
        al[3] = frag_ld(&Qls[0][0], rr + 8, 2*ks+1, lane);
#pragma unroll
        for (int nf = 0; nf < 8; nf++) {
            int nr = nf * 8;
            u32 bh0 = frag_ld(&Khs[0][0], nr, 2*ks,   lane);
            u32 bh1 = frag_ld(&Khs[0][0], nr, 2*ks+1, lane);
            u32 bl0 = frag_ld(&Kls[0][0], nr, 2*ks,   lane);
            u32 bl1 = frag_ld(&Kls[0][0], nr, 2*ks+1, lane);
            mma_bf16(acc[nf], ah, bh0, bh1);
            mma_bf16(acc[nf], ah, bl0, bl1);
            mma_bf16(acc[nf], al, bh0, bh1);
        }
    }
#pragma unroll
    for (int nf = 0; nf < 8; nf++) {
        int col = mk0 + nf * 8 + (lane & 3) * 2;
        int r0 = mq0 + warp * 16 + (lane >> 2);
        *(float2*)(Sb + (size_t)r0 * Nk + col)       = make_float2(acc[nf][0], acc[nf][1]);
        *(float2*)(Sb + (size_t)(r0 + 8) * Nk + col) = make_float2(acc[nf][2], acc[nf][3]);
    }
}

// ================= fuse MLP + softmax (bf16 split output) =================
template<int NK, int QPB>
__global__ __launch_bounds__(256) void fuse_softmax_kernel(
    const float* __restrict__ S, const float* __restrict__ aux,
    bf16* __restrict__ Ph, bf16* __restrict__ Pl,
    const float* __restrict__ W1, const float* __restrict__ b1,
    const float* __restrict__ W2, const float* __restrict__ b2,
    int Nq, int qn_off, int qm_off)
{
    __shared__ __align__(16) u64 sW1d[16][16];
    __shared__ __align__(16) u64 sW2d[16][8];
    __shared__ u64 sb1d[16], sb2d[8];
    __shared__ __align__(16) float fs[QPB][8][NK];
    const int tid = threadIdx.x;
    { int j = tid >> 4, c = tid & 15; float w = W1[c * 16 + j]; sW1d[j][c] = pk2(w, w); }
    if (tid < 128) { int j = tid >> 3, h = tid & 7; float w = W2[j * 8 + h]; sW2d[j][h] = pk2(w, w); }
    if (tid < 16)  { float w = b1[tid]; sb1d[tid] = pk2(w, w); }
    if (tid < 8)   { float w = b2[tid]; sb2d[tid] = pk2(w, w); }
    __syncthreads();

    const int nblocks = Nq / QPB;
    const int nb = blockIdx.x % nblocks;
    const int b  = blockIdx.x / nblocks;
    constexpr int TPQ = 256 / QPB;
    const int ql = tid / TPQ;
    const int tl = tid % TPQ;
    const int n  = nb * QPB + ql;
    const int m0 = tl * 4;

    if (m0 < NK) {
        u64 x2[16][2];
#pragma unroll
        for (int h = 0; h < 8; h++) {
            ulonglong2 v = *(const ulonglong2*)(S + ((size_t)(h * Bb + b) * Nq + n) * NK + m0);
            x2[h][0] = v.x; x2[h][1] = v.y;
            ulonglong2 w = *(const ulonglong2*)(aux + ((size_t)(h * Bb + b) * Qq + qn_off + n) * Qq + qm_off + m0);
            x2[8 + h][0] = w.x; x2[8 + h][1] = w.y;
        }
        u64 f0[8], f1[8];
#pragma unroll
        for (int h = 0; h < 8; h++) { f0[h] = sb2d[h]; f1[h] = f0[h]; }
#pragma unroll
        for (int j = 0; j < 16; j++) {
            u64 h0 = sb1d[j], h1 = h0;
            ulonglong2 w1p[8];
#pragma unroll
            for (int p = 0; p < 8; p++) w1p[p] = *(const ulonglong2*)&sW1d[j][p * 2];
#pragma unroll
            for (int c = 0; c < 16; c++) {
                u64 wv = (c & 1) ? w1p[c >> 1].y : w1p[c >> 1].x;
                h0 = fma2(x2[c][0], wv, h0);
                h1 = fma2(x2[c][1], wv, h1);
            }
            float2 ra = up2(h0), rb = up2(h1);
            ra.x = fmaxf(ra.x, 0.f); ra.y = fmaxf(ra.y, 0.f);
            rb.x = fmaxf(rb.x, 0.f); rb.y = fmaxf(rb.y, 0.f);
            u64 r0 = pk2(ra.x, ra.y), r1 = pk2(rb.x, rb.y);
            ulonglong2 w2p[4];
#pragma unroll
            for (int p = 0; p < 4; p++) w2p[p] = *(const ulonglong2*)&sW2d[j][p * 2];
#pragma unroll
            for (int h = 0; h < 8; h++) {
                u64 wv = (h & 1) ? w2p[h >> 1].y : w2p[h >> 1].x;
                f0[h] = fma2(r0, wv, f0[h]);
                f1[h] = fma2(r1, wv, f1[h]);
            }
        }
#pragma unroll
        for (int h = 0; h < 8; h++) {
            ulonglong2 st; st.x = f0[h]; st.y = f1[h];
            *(ulonglong2*)&fs[ql][h][m0] = st;
        }
    }
    __syncthreads();

    const int warp = tid >> 5, lane = tid & 31;
    constexpr int R = QPB * 8;
    for (int row = warp; row < R; row += 8) {
        int qr = row >> 3;
        int hr = row & 7;
        float* frow = fs[qr][hr];
        float mx = -3.0e38f;
        for (int m = lane; m < NK; m += 32) mx = fmaxf(mx, frow[m]);
#pragma unroll
        for (int o = 16; o > 0; o >>= 1) mx = fmaxf(mx, __shfl_xor_sync(0xffffffffu, mx, o));
        float sum = 0.f;
        for (int m = lane; m < NK; m += 32) {
            float ev = __expf(frow[m] - mx);
            frow[m] = ev;
            sum += ev;
        }
#pragma unroll
        for (int o = 16; o > 0; o >>= 1) sum += __shfl_xor_sync(0xffffffffu, sum, o);
        float inv = 1.f / sum;
        size_t base = ((size_t)(hr * Bb + b) * Nq + nb * QPB + qr) * NK;
        for (int m = lane; m < NK; m += 32) {
            float p = frow[m] * inv;
            bf16 h = __float2bfloat16(p);
            Ph[base + m] = h;
            Pl[base + m] = __float2bfloat16(p - __bfloat162float(h));
        }
    }
}

// ================= AV HMMA =================
struct AVArgs {
    const bf16 *P1h, *P1l, *P2h, *P2l, *P3h, *P3l;
    const bf16 *Vtch, *Vtcl, *Vtsh, *Vtsl;
    float* heads;
    int which;   // 0 = av1+av3, 1 = av2 (accumulate)
};
__global__ __launch_bounds__(128) void av_hmma(AVArgs a)
{
    __shared__ __align__(16) bf16 Phs[64][ASTR], Pls[64][ASTR];
    __shared__ __align__(16) bf16 Vhs[32][ASTR], Vls[32][ASTR];
    const int x = blockIdx.x, z = blockIdx.y;
    const int hh = z >> 4, bb = z & 15;
    const bf16 *Ph, *Pl, *Vh, *Vl;
    int Nq, Nk, n0, qoff, TLv, accum;
    if (a.which == 0) {
        if (x < 7) { Ph = a.P1h; Pl = a.P1l; Vh = a.Vtch; Vl = a.Vtcl;
                     Nq = Tt; Nk = Tt; n0 = x * 64; qoff = S1c; TLv = Tt; accum = 0; }
        else       { Ph = a.P3h; Pl = a.P3l; Vh = a.Vtch; Vl = a.Vtcl;
                     Nq = S1c; Nk = Tt; n0 = 0; qoff = 0; TLv = Tt; accum = 0; }
    } else {
        Ph = a.P2h; Pl = a.P2l; Vh = a.Vtsh; Vl = a.Vtsl;
        Nq = Tt; Nk = S1c; n0 = x * 64; qoff = S1c; TLv = S1c; accum = 1;
    }
    const int tid = threadIdx.x;
    const int warp = tid >> 5, lane = tid & 31;

    float acc[4][4];
#pragma unroll
    for (int nf = 0; nf < 4; nf++)
#pragma unroll
        for (int j = 0; j < 4; j++) acc[nf][j] = 0.f;

    for (int k0 = 0; k0 < Nk; k0 += 32) {
        if (k0) __syncthreads();
        {
            int rr = tid & 63;
            int sel = tid >> 6;
            int rsw = (rr >> 3) & 3;
            const uint4* ps = (const uint4*)((sel ? Pl : Ph) + ((size_t)z * Nq + n0 + rr) * Nk + k0);
            bf16 (*Pd)[ASTR] = sel ? Pls : Phs;
#pragma unroll
            for (int g = 0; g < 4; g++) {
                int pg = ((g + rsw) & 3) << 3;
                *(uint4*)&Pd[rr][pg] = ps[g];
            }
        }
        if (tid < 64) {
            int rr = tid & 31;
            int sel = tid >> 5;
            int rsw = (rr >> 3) & 3;
            const uint4* vs = (const uint4*)((sel ? Vl : Vh) + ((size_t)z * 32 + rr) * TLv + k0);
            bf16 (*Vd)[ASTR] = sel ? Vls : Vhs;
#pragma unroll
            for (int g = 0; g < 4; g++) {
                int pg = ((g + rsw) & 3) << 3;
                *(uint4*)&Vd[rr][pg] = vs[g];
            }
        }
        __syncthreads();
        const int rr = warp * 16;
#pragma unroll
        for (int ks = 0; ks < 2; ks++) {
            u32 ah[4], al[4];
            ah[0] = frag_ld(&Phs[0][0], rr,     2*ks,   lane);
            ah[1] = frag_ld(&Phs[0][0], rr + 8, 2*ks,   lane);
            ah[2] = frag_ld(&Phs[0][0], rr,     2*ks+1, lane);
            ah[3] = frag_ld(&Phs[0][0], rr + 8, 2*ks+1, lane);
            al[0] = frag_ld(&Pls[0][0], rr,     2*ks,   lane);
            al[1] = frag_ld(&Pls[0][0], rr + 8, 2*ks,   lane);
            al[2] = frag_ld(&Pls[0][0], rr,     2*ks+1, lane);
            al[3] = frag_ld(&Pls[0][0], rr + 8, 2*ks+1, lane);
#pragma unroll
            for (int nf = 0; nf < 4; nf++) {
                int nr = nf * 8;
                u32 bh0 = frag_ld(&Vhs[0][0], nr, 2*ks,   lane);
                u32 bh1 = frag_ld(&Vhs[0][0], nr, 2*ks+1, lane);
                u32 bl0 = frag_ld(&Vls[0][0], nr, 2*ks,   lane);
                u32 bl1 = frag_ld(&Vls[0][0], nr, 2*ks+1, lane);
                mma_bf16(acc[nf], ah, bh0, bh1);
                mma_bf16(acc[nf], ah, bl0, bl1);
                mma_bf16(acc[nf], al, bh0, bh1);
            }
        }
    }
#pragma unroll
    for (int nf = 0; nf < 4; nf++) {
        int e = nf * 8 + (lane & 3) * 2;
        int r0 = n0 + warp * 16 + (lane >> 2);
#pragma unroll
        for (int half = 0; half < 2; half++) {
            int rq = r0 + half * 8;
            float2 v = half ? make_float2(acc[nf][2], acc[nf][3])
                            : make_float2(acc[nf][0], acc[nf][1]);
            float* dst = a.heads + ((size_t)(bb * Qq + qoff + rq)) * 256 + hh * 32 + e;
            if (accum) { float2 o = *(float2*)dst; v.x += o.x; v.y += o.y; }
            *(float2*)dst = v;
        }
    }
}

// ---------------- launch ----------------
extern "C" void kernel_launch(void* const* d_in, const int* in_sizes, int n_in,
                              void* d_out, int out_size)
{
    const float* h_fea      = (const float*)d_in[0];
    const float* aux        = (const float*)d_in[1];
    const float* Wq_custom  = (const float*)d_in[2];
    const float* Wq_custom1 = (const float*)d_in[3];
    const float* Wk_custom  = (const float*)d_in[4];
    const float* Wv_custom  = (const float*)d_in[5];
    const float* Wq_charge1 = (const float*)d_in[6];
    const float* Wk_charge  = (const float*)d_in[7];
    const float* Wv_charge  = (const float*)d_in[8];
    const float* W1         = (const float*)d_in[9];
    const float* b1         = (const float*)d_in[10];
    const float* W2         = (const float*)d_in[11];
    const float* b2         = (const float*)d_in[12];
    const float* W_out      = (const float*)d_in[13];
    float* out = (float*)d_out;

    float *P1, *P2, *P3, *heads;
    bf16 *Xhi, *Xlo, *Hhi, *Hlo, *Wbh, *Wbl;
    bf16 *Q1h, *Q1l, *Q0h, *Q0l, *Kch, *Kcl, *Vch, *Vcl;
    bf16 *Qsh, *Qsl, *Ksh, *Ksl, *Vsh, *Vsl;
    bf16 *Vtch, *Vtcl, *Vtsh, *Vtsl;
    bf16 *P1h, *P1l, *P2h, *P2l, *P3h, *P3l;
    cudaGetSymbolAddress((void**)&P1, g_P1);
    cudaGetSymbolAddress((void**)&P2, g_P2);
    cudaGetSymbolAddress((void**)&P3, g_P3);
    cudaGetSymbolAddress((void**)&heads, g_heads);
    cudaGetSymbolAddress((void**)&Xhi, g_Xhi);
    cudaGetSymbolAddress((void**)&Xlo, g_Xlo);
    cudaGetSymbolAddress((void**)&Hhi, g_Hhi);
    cudaGetSymbolAddress((void**)&Hlo, g_Hlo);
    cudaGetSymbolAddress((void**)&Wbh, g_Wbh);
    cudaGetSymbolAddress((void**)&Wbl, g_Wbl);
    cudaGetSymbolAddress((void**)&Q1h, g_Q1h);  cudaGetSymbolAddress((void**)&Q1l, g_Q1l);
    cudaGetSymbolAddress((void**)&Q0h, g_Q0h);  cudaGetSymbolAddress((void**)&Q0l, g_Q0l);
    cudaGetSymbolAddress((void**)&Kch, g_Kch);  cudaGetSymbolAddress((void**)&Kcl, g_Kcl);
    cudaGetSymbolAddress((void**)&Vch, g_Vch);  cudaGetSymbolAddress((void**)&Vcl, g_Vcl);
    cudaGetSymbolAddress((void**)&Qsh, g_Qsh);  cudaGetSymbolAddress((void**)&Qsl, g_Qsl);
    cudaGetSymbolAddress((void**)&Ksh, g_Ksh);  cudaGetSymbolAddress((void**)&Ksl, g_Ksl);
    cudaGetSymbolAddress((void**)&Vsh, g_Vsh);  cudaGetSymbolAddress((void**)&Vsl, g_Vsl);
    cudaGetSymbolAddress((void**)&Vtch, g_Vtch); cudaGetSymbolAddress((void**)&Vtcl, g_Vtcl);
    cudaGetSymbolAddress((void**)&Vtsh, g_Vtsh); cudaGetSymbolAddress((void**)&Vtsl, g_Vtsl);
    cudaGetSymbolAddress((void**)&P1h, g_P1h);  cudaGetSymbolAddress((void**)&P1l, g_P1l);
    cudaGetSymbolAddress((void**)&P2h, g_P2h);  cudaGetSymbolAddress((void**)&P2l, g_P2l);
    cudaGetSymbolAddress((void**)&P3h, g_P3h);  cudaGetSymbolAddress((void**)&P3l, g_P3l);

    // 1. input/weight splits
    cvt_split_kernel<<<(Bb*Qq*Dd/4 + 255)/256, 256>>>(h_fea, Xhi, Xlo, Bb*Qq*Dd/4);
    WArgs wa;
    wa.W[0] = Wq_custom1; wa.W[1] = Wq_custom; wa.W[2] = Wk_custom; wa.W[3] = Wv_custom;
    wa.W[4] = Wq_charge1; wa.W[5] = Wk_charge; wa.W[6] = Wv_charge; wa.W[7] = W_out;
    cvt_w_kernel<<<8*256*256/256, 256>>>(wa, Wbh, Wbl);

    // 2. merged projections (bf16 split outputs only)
    HArgs hp;
    hp.Ahi = Xhi; hp.Alo = Xlo; hp.Bh = Wbh; hp.Bl = Wbl;
    hp.Ofp = nullptr; hp.mode = 0;
    hp.Oh[0] = Q1h; hp.Ol[0] = Q1l;
    hp.Oh[1] = Q0h; hp.Ol[1] = Q0l;
    hp.Oh[2] = Kch; hp.Ol[2] = Kcl;
    hp.Oh[3] = Vch; hp.Ol[3] = Vcl;
    hp.Oh[4] = Qsh; hp.Ol[4] = Qsl;
    hp.Oh[5] = Ksh; hp.Ol[5] = Ksl;
    hp.Oh[6] = Vsh; hp.Ol[6] = Vsl;
    hmma_kernel<<<dim3(64, 16), 128>>>(hp);

    // 3. V transpose
    VtArgs va;
    va.srcH[0] = Vch; va.srcL[0] = Vcl; va.dstH[0] = Vtch; va.dstL[0] = Vtcl; va.TL[0] = Tt;
    va.srcH[1] = Vsh; va.srcL[1] = Vsl; va.dstH[1] = Vtsh; va.dstL[1] = Vtsl; va.TL[1] = S1c;
    vt_kernel<<<2048, 256>>>(va);

    // 4. QK^T (all three jobs)
    QKArgs qa;
    qa.Q1h = Q1h; qa.Q1l = Q1l; qa.Q0h = Q0h; qa.Q0l = Q0l; qa.Qsh = Qsh; qa.Qsl = Qsl;
    qa.Kch = Kch; qa.Kcl = Kcl; qa.Ksh = Ksh; qa.Ksl = Ksl;
    qa.P1 = P1; qa.P2 = P2; qa.P3 = P3;
    qk_hmma<<<dim3(63, 128), 128>>>(qa);

    // 5. fuse MLP + softmax -> bf16 split probabilities
    fuse_softmax_kernel<448, 2><<<Bb * (Tt / 2),  256>>>(P1, aux, P1h, P1l, W1, b1, W2, b2, Tt,  S1c, S1c);
    fuse_softmax_kernel<64, 16><<<Bb * (Tt / 16), 256>>>(P2, aux, P2h, P2l, W1, b1, W2, b2, Tt,  S1c, 0);
    fuse_softmax_kernel<448, 2><<<Bb * (S1c / 2), 256>>>(P3, aux, P3h, P3l, W1, b1, W2, b2, S1c, 0,   S1c);

    // 6. AV on tensor cores
    AVArgs aa;
    aa.P1h = P1h; aa.P1l = P1l; aa.P2h = P2h; aa.P2l = P2l; aa.P3h = P3h; aa.P3l = P3l;
    aa.Vtch = Vtch; aa.Vtcl = Vtcl; aa.Vtsh = Vtsh; aa.Vtsl = Vtsl;
    aa.heads = heads;
    aa.which = 0;
    av_hmma<<<dim3(8, 128), 128>>>(aa);
    AVArgs ab = aa; ab.which = 1;
    av_hmma<<<dim3(7, 128), 128>>>(ab);

    // 7. output GEMM
    cvt_split_kernel<<<(Bb*Qq*Dd/4 + 255)/256, 256>>>(heads, Hhi, Hlo, Bb*Qq*Dd/4);
    HArgs ho;
    ho.Ahi = Hhi; ho.Alo = Hlo; ho.Bh = Wbh; ho.Bl = Wbl;
    ho.Ofp = out; ho.mode = 1;
    for (int i = 0; i < 7; i++) { ho.Oh[i] = nullptr; ho.Ol[i] = nullptr; }
    hmma_kernel<<<dim3(64, 4), 128>>>(ho);
}

// round 12
// speedup vs baseline: 1.5906x; 1.0669x over previous
#include <cuda_runtime.h>
#include <cuda_bf16.h>

#define Hh  8
#define Dd  256
#define HDe 32
#define Bb  16
#define Qq  512
#define S1c 64
#define Tt  448

typedef unsigned long long u64;
typedef unsigned int u32;
typedef __nv_bfloat16  bf16;
typedef __nv_bfloat162 bf162;

// ---- packed f32x2 helpers (fuse kernel) ----
__device__ __forceinline__ u64 pk2(float x, float y) {
    u64 r; asm("mov.b64 %0, {%1, %2};" : "=l"(r) : "f"(x), "f"(y)); return r;
}
__device__ __forceinline__ float2 up2(u64 v) {
    float2 r; asm("mov.b64 {%0, %1}, %2;" : "=f"(r.x), "=f"(r.y) : "l"(v)); return r;
}
__device__ __forceinline__ u64 fma2(u64 a, u64 b, u64 c) {
    u64 d; asm("fma.rn.f32x2 %0, %1, %2, %3;" : "=l"(d) : "l"(a), "l"(b), "l"(c)); return d;
}

// ---------------- static scratch ----------------
__device__ float g_P1[128*Tt*Tt];
__device__ float g_P2[128*Tt*S1c];
__device__ float g_P3[128*S1c*Tt];
__device__ float g_heads[Bb*Qq*Dd];

__device__ bf16 g_Xhi[Bb*Qq*Dd], g_Xlo[Bb*Qq*Dd];
__device__ bf16 g_Hhi[Bb*Qq*Dd], g_Hlo[Bb*Qq*Dd];
__device__ bf16 g_Wbh[8*256*256], g_Wbl[8*256*256];

// proj bf16 splits, layout [(h*16+b)*TL + n]*32 + e
__device__ bf16 g_Q1h[128*Tt*32],  g_Q1l[128*Tt*32];
__device__ bf16 g_Q0h[128*Tt*32],  g_Q0l[128*Tt*32];
__device__ bf16 g_Kch[128*Tt*32],  g_Kcl[128*Tt*32];
__device__ bf16 g_Vch[128*Tt*32],  g_Vcl[128*Tt*32];
__device__ bf16 g_Qsh[128*S1c*32], g_Qsl[128*S1c*32];
__device__ bf16 g_Ksh[128*S1c*32], g_Ksl[128*S1c*32];
__device__ bf16 g_Vsh[128*S1c*32], g_Vsl[128*S1c*32];

// probabilities bf16 splits
__device__ bf16 g_P1h[128*Tt*Tt],  g_P1l[128*Tt*Tt];
__device__ bf16 g_P2h[128*Tt*S1c], g_P2l[128*Tt*S1c];
__device__ bf16 g_P3h[128*S1c*Tt], g_P3l[128*S1c*Tt];

// ================= conversion kernels =================
__global__ __launch_bounds__(256) void cvt_split_kernel(
    const float* __restrict__ src, bf16* __restrict__ hi,
    bf16* __restrict__ lo, int n4)
{
    int i = blockIdx.x * 256 + threadIdx.x;
    if (i >= n4) return;
    float4 v = ((const float4*)src)[i];
    bf16 h0 = __float2bfloat16(v.x), h1 = __float2bfloat16(v.y);
    bf16 h2 = __float2bfloat16(v.z), h3 = __float2bfloat16(v.w);
    ((bf162*)hi)[i*2]   = bf162(h0, h1);
    ((bf162*)hi)[i*2+1] = bf162(h2, h3);
    ((bf162*)lo)[i*2]   = bf162(__float2bfloat16(v.x - __bfloat162float(h0)),
                                __float2bfloat16(v.y - __bfloat162float(h1)));
    ((bf162*)lo)[i*2+1] = bf162(__float2bfloat16(v.z - __bfloat162float(h2)),
                                __float2bfloat16(v.w - __bfloat162float(h3)));
}

struct WArgs { const float* W[8]; };

__global__ __launch_bounds__(256) void cvt_w_kernel(
    WArgs wa, bf16* __restrict__ bh, bf16* __restrict__ bl)
{
    int i = blockIdx.x * 256 + threadIdx.x;
    int s = i >> 16;
    int r = i & 65535;
    int c = r >> 8, k = r & 255;
    const float* W = wa.W[s];
    float x = (s < 7) ? W[(c >> 5) * 8192 + k * 32 + (c & 31)] : W[k * 256 + c];
    bf16 h = __float2bfloat16(x);
    bh[i] = h;
    bl[i] = __float2bfloat16(x - __bfloat162float(h));
}

// ================= shared HMMA machinery =================
#define ASTR 40

__device__ __forceinline__ u32 smaddr(const void* p) {
    return (u32)__cvta_generic_to_shared(p);
}
__device__ __forceinline__ void ldsm4(u32& r0, u32& r1, u32& r2, u32& r3, u32 a) {
    asm volatile("ldmatrix.sync.aligned.m8n8.x4.shared.b16 {%0,%1,%2,%3},[%4];"
        : "=r"(r0), "=r"(r1), "=r"(r2), "=r"(r3) : "r"(a));
}
__device__ __forceinline__ void ldsm4t(u32& r0, u32& r1, u32& r2, u32& r3, u32 a) {
    asm volatile("ldmatrix.sync.aligned.m8n8.x4.trans.shared.b16 {%0,%1,%2,%3},[%4];"
        : "=r"(r0), "=r"(r1), "=r"(r2), "=r"(r3) : "r"(a));
}

// A-frag x4: 16 rows (R0..R0+15) x k16 (ks chunk). regs = a0..a3.
__device__ __forceinline__ void ldA(u32* a, const bf16 (*M)[ASTR], int R0, int ks, int lane) {
    int row = R0 + ((lane >> 3) & 1) * 8 + (lane & 7);
    int kg  = 2 * ks + (lane >> 4);
    ldsm4(a[0], a[1], a[2], a[3], smaddr(&M[row][((kg + (row >> 3)) & 3) << 3]));
}
// B-frag x4 from n-major smem: 2 nf (N0..N0+15) at ks. regs = b0nf0,b1nf0,b0nf1,b1nf1.
__device__ __forceinline__ void ldB(u32* b, const bf16 (*M)[ASTR], int N0, int ks, int lane) {
    int row = N0 + (lane >> 4) * 8 + (lane & 7);
    int kg  = 2 * ks + ((lane >> 3) & 1);
    ldsm4(b[0], b[1], b[2], b[3], smaddr(&M[row][((kg + (row >> 3)) & 3) << 3]));
}
// B-frag x4 via trans from k-major smem (V[t][e]): 2 nf (eg pair E0=nfp*16 cols) at ks.
__device__ __forceinline__ void ldBt(u32* b, const bf16 (*M)[ASTR], int nfp, int ks, int lane) {
    int row = ks * 16 + ((lane >> 3) & 1) * 8 + (lane & 7);
    int eg  = nfp * 2 + (lane >> 4);
    ldsm4t(b[0], b[1], b[2], b[3], smaddr(&M[row][((eg + (row >> 3)) & 3) << 3]));
}

__device__ __forceinline__ void mma_bf16(float* d, const u32* a, u32 b0, u32 b1) {
    asm volatile(
        "mma.sync.aligned.m16n8k16.row.col.f32.bf16.bf16.f32 "
        "{%0,%1,%2,%3}, {%4,%5,%6,%7}, {%8,%9}, {%0,%1,%2,%3};"
        : "+f"(d[0]), "+f"(d[1]), "+f"(d[2]), "+f"(d[3])
        : "r"(a[0]), "r"(a[1]), "r"(a[2]), "r"(a[3]), "r"(b0), "r"(b1));
}

__device__ __forceinline__ void split_st(bf16* hp, bf16* lp, size_t idx, float2 v) {
    bf16 h0 = __float2bfloat16(v.x), h1 = __float2bfloat16(v.y);
    *(bf162*)(hp + idx) = bf162(h0, h1);
    *(bf162*)(lp + idx) = bf162(__float2bfloat16(v.x - __bfloat162float(h0)),
                                __float2bfloat16(v.y - __bfloat162float(h1)));
}

// ================= proj/out HMMA kernel =================
struct HArgs {
    const bf16 *Ahi, *Alo;
    const bf16 *Bh, *Bl;
    float* Ofp;
    bf16 *Oh[7], *Ol[7];
    int mode;
};

__global__ __launch_bounds__(128) void hmma_kernel(HArgs args)
{
    __shared__ __align__(16) bf16 Ah[128][ASTR], Al[128][ASTR];
    __shared__ __align__(16) bf16 Bhs[64][ASTR], Bls[64][ASTR];
    const int x = blockIdx.x, y = blockIdx.y;
    int set, col0, TL, qoff, m0;
    if (args.mode == 0) {
        if (x < 56) { set = y >> 2; col0 = (y & 3) * 64; TL = Tt; qoff = S1c; m0 = x * 128; }
        else {
            if (y >= 12) return;
            set = 4 + (y >> 2); col0 = (y & 3) * 64; TL = S1c; qoff = 0; m0 = (x - 56) * 128;
        }
    } else { set = 7; col0 = y * 64; TL = Qq; qoff = 0; m0 = x * 128; }

    const int tid = threadIdx.x;
    const int warp = tid >> 5, lane = tid & 31;

    float acc[2][8][4];
#pragma unroll
    for (int mf = 0; mf < 2; mf++)
#pragma unroll
        for (int nf = 0; nf < 8; nf++)
#pragma unroll
            for (int j = 0; j < 4; j++) acc[mf][nf][j] = 0.f;

    int t = m0 + tid;
    int ab = t / TL;
    size_t arow = ((size_t)ab * Qq + qoff + (t - ab * TL)) * 256;
    const int br = tid & 63;
    const bf16* Bsrc = ((tid < 64) ? args.Bh : args.Bl) + (size_t)set * 65536 + (size_t)(col0 + br) * 256;
    const int rswA = (tid >> 3) & 3;
    const int rswB = (br >> 3) & 3;

    for (int k0 = 0; k0 < 256; k0 += 32) {
        if (k0) __syncthreads();
        const uint4* sAh = (const uint4*)(args.Ahi + arow + k0);
        const uint4* sAl = (const uint4*)(args.Alo + arow + k0);
#pragma unroll
        for (int g = 0; g < 4; g++) {
            int pg = ((g + rswA) & 3) << 3;
            *(uint4*)&Ah[tid][pg] = sAh[g];
            *(uint4*)&Al[tid][pg] = sAl[g];
        }
        {
            const uint4* sB = (const uint4*)(Bsrc + k0);
            bf16 (*Bd)[ASTR] = (tid < 64) ? Bhs : Bls;
#pragma unroll
            for (int g = 0; g < 4; g++) {
                int pg = ((g + rswB) & 3) << 3;
                *(uint4*)&Bd[br][pg] = sB[g];
            }
        }
        __syncthreads();
#pragma unroll
        for (int ks = 0; ks < 2; ks++) {
            u32 ah[2][4], al[2][4];
            ldA(ah[0], Ah, warp * 32,      ks, lane);
            ldA(ah[1], Ah, warp * 32 + 16, ks, lane);
            ldA(al[0], Al, warp * 32,      ks, lane);
            ldA(al[1], Al, warp * 32 + 16, ks, lane);
#pragma unroll
            for (int np = 0; np < 4; np++) {
                u32 bh[4], bl[4];
                ldB(bh, Bhs, np * 16, ks, lane);
                ldB(bl, Bls, np * 16, ks, lane);
#pragma unroll
                for (int q = 0; q < 2; q++) {
                    int nf = np * 2 + q;
#pragma unroll
                    for (int mf = 0; mf < 2; mf++) {
                        mma_bf16(acc[mf][nf], ah[mf], bh[2*q], bh[2*q+1]);
                        mma_bf16(acc[mf][nf], ah[mf], bl[2*q], bl[2*q+1]);
                        mma_bf16(acc[mf][nf], al[mf], bh[2*q], bh[2*q+1]);
                    }
                }
            }
        }
    }

#pragma unroll
    for (int mf = 0; mf < 2; mf++) {
#pragma unroll
        for (int nf = 0; nf < 8; nf++) {
            int lc = nf * 8 + (lane & 3) * 2;
            int t0 = m0 + warp * 32 + mf * 16 + (lane >> 2);
            int t1 = t0 + 8;
            float2 v0 = make_float2(acc[mf][nf][0], acc[mf][nf][1]);
            float2 v1 = make_float2(acc[mf][nf][2], acc[mf][nf][3]);
            if (args.mode == 0) {
                int c = col0 + lc;
                int h = c >> 5, e = c & 31;
                int b0i = t0 / TL, n0i = t0 - b0i * TL;
                int b1i = t1 / TL, n1i = t1 - b1i * TL;
                size_t i0 = (((size_t)h * Bb + b0i) * TL + n0i) * 32 + e;
                size_t i1 = (((size_t)h * Bb + b1i) * TL + n1i) * 32 + e;
                split_st(args.Oh[set], args.Ol[set], i0, v0);
                split_st(args.Oh[set], args.Ol[set], i1, v1);
            } else {
                int d = col0 + lc;
                *(float2*)(args.Ofp + (size_t)t0 * 256 + d) = v0;
                *(float2*)(args.Ofp + (size_t)t1 * 256 + d) = v1;
            }
        }
    }
}

// ================= QK^T HMMA =================
struct QKArgs {
    const bf16 *Q1h, *Q1l, *Q0h, *Q0l, *Qsh, *Qsl;
    const bf16 *Kch, *Kcl, *Ksh, *Ksl;
    float *P1, *P2, *P3;
};
__global__ __launch_bounds__(128) void qk_hmma(QKArgs a)
{
    __shared__ __align__(16) bf16 Qhs[64][ASTR], Qls[64][ASTR];
    __shared__ __align__(16) bf16 Khs[64][ASTR], Kls[64][ASTR];
    const int x = blockIdx.x, z = blockIdx.y;
    const bf16 *Qh, *Ql, *Kh, *Kl;
    float* Sb;
    int Nq, Nk, mq0, mk0;
    if (x < 49) {
        Qh = a.Q1h; Ql = a.Q1l; Kh = a.Kch; Kl = a.Kcl;
        Sb = a.P1 + (size_t)z * Tt * Tt; Nq = Tt; Nk = Tt;
        mq0 = (x / 7) * 64; mk0 = (x % 7) * 64;
    } else if (x < 56) {
        Qh = a.Q0h; Ql = a.Q0l; Kh = a.Ksh; Kl = a.Ksl;
        Sb = a.P2 + (size_t)z * Tt * S1c; Nq = Tt; Nk = S1c;
        mq0 = (x - 49) * 64; mk0 = 0;
    } else {
        Qh = a.Qsh; Ql = a.Qsl; Kh = a.Kch; Kl = a.Kcl;
        Sb = a.P3 + (size_t)z * S1c * Tt; Nq = S1c; Nk = Tt;
        mq0 = 0; mk0 = (x - 56) * 64;
    }
    const int tid = threadIdx.x;
    const int warp = tid >> 5, lane = tid & 31;
    {
        int rr = tid & 63;
        int sel = tid >> 6;
        int rsw = (rr >> 3) & 3;
        const uint4* qs = (const uint4*)((sel ? Ql : Qh) + ((size_t)z * Nq + mq0 + rr) * 32);
        const uint4* ks = (const uint4*)((sel ? Kl : Kh) + ((size_t)z * Nk + mk0 + rr) * 32);
        bf16 (*Qd)[ASTR] = sel ? Qls : Qhs;
        bf16 (*Kd)[ASTR] = sel ? Kls : Khs;
#pragma unroll
        for (int g = 0; g < 4; g++) {
            int pg = ((g + rsw) & 3) << 3;
            *(uint4*)&Qd[rr][pg] = qs[g];
            *(uint4*)&Kd[rr][pg] = ks[g];
        }
    }
    __syncthreads();

    float acc[8][4];
#pragma unroll
    for (int nf = 0; nf < 8; nf++)
#pragma unroll
        for (int j = 0; j < 4; j++) acc[nf][j] = 0.f;

#pragma unroll
    for (int ks = 0; ks < 2; ks++) {
        u32 ah[4], al[4];
        ldA(ah, Qhs, warp * 16, ks, lane);
        ldA(al, Qls, warp * 16, ks, lane);
#pragma unroll
        for (int np = 0; np < 4; np++) {
            u32 bh[4], bl[4];
            ldB(bh, Khs, np * 16, ks, lane);
            ldB(bl, Kls, np * 16, ks, lane);
#pragma unroll
            for (int q = 0; q < 2; q++) {
                int nf = np * 2 + q;
                mma_bf16(acc[nf], ah, bh[2*q], bh[2*q+1]);
                mma_bf16(acc[nf], ah, bl[2*q], bl[2*q+1]);
                mma_bf16(acc[nf], al, bh[2*q], bh[2*q+1]);
            }
        }
    }
#pragma unroll
    for (int nf = 0; nf < 8; nf++) {
        int col = mk0 + nf * 8 + (lane & 3) * 2;
        int r0 = mq0 + warp * 16 + (lane >> 2);
        *(float2*)(Sb + (size_t)r0 * Nk + col)       = make_float2(acc[nf][0], acc[nf][1]);
        *(float2*)(Sb + (size_t)(r0 + 8) * Nk + col) = make_float2(acc[nf][2], acc[nf][3]);
    }
}

// ================= fuse MLP + softmax (bf16 split output) =================
template<int NK, int QPB>
__global__ __launch_bounds__(256) void fuse_softmax_kernel(
    const float* __restrict__ S, const float* __restrict__ aux,
    bf16* __restrict__ Ph, bf16* __restrict__ Pl,
    const float* __restrict__ W1, const float* __restrict__ b1,
    const float* __restrict__ W2, const float* __restrict__ b2,
    int Nq, int qn_off, int qm_off)
{
    __shared__ __align__(16) u64 sW1d[16][16];
    __shared__ __align__(16) u64 sW2d[16][8];
    __shared__ u64 sb1d[16], sb2d[8];
    __shared__ __align__(16) float fs[QPB][8][NK];
    const int tid = threadIdx.x;
    { int j = tid >> 4, c = tid & 15; float w = W1[c * 16 + j]; sW1d[j][c] = pk2(w, w); }
    if (tid < 128) { int j = tid >> 3, h = tid & 7; float w = W2[j * 8 + h]; sW2d[j][h] = pk2(w, w); }
    if (tid < 16)  { float w = b1[tid]; sb1d[tid] = pk2(w, w); }
    if (tid < 8)   { float w = b2[tid]; sb2d[tid] = pk2(w, w); }
    __syncthreads();

    const int nblocks = Nq / QPB;
    const int nb = blockIdx.x % nblocks;
    const int b  = blockIdx.x / nblocks;
    constexpr int TPQ = 256 / QPB;
    const int ql = tid / TPQ;
    const int tl = tid % TPQ;
    const int n  = nb * QPB + ql;
    const int m0 = tl * 4;

    if (m0 < NK) {
        u64 x2[16][2];
#pragma unroll
        for (int h = 0; h < 8; h++) {
            ulonglong2 v = *(const ulonglong2*)(S + ((size_t)(h * Bb + b) * Nq + n) * NK + m0);
            x2[h][0] = v.x; x2[h][1] = v.y;
            ulonglong2 w = *(const ulonglong2*)(aux + ((size_t)(h * Bb + b) * Qq + qn_off + n) * Qq + qm_off + m0);
            x2[8 + h][0] = w.x; x2[8 + h][1] = w.y;
        }
        u64 f0[8], f1[8];
#pragma unroll
        for (int h = 0; h < 8; h++) { f0[h] = sb2d[h]; f1[h] = f0[h]; }
#pragma unroll
        for (int j = 0; j < 16; j++) {
            u64 h0 = sb1d[j], h1 = h0;
            ulonglong2 w1p[8];
#pragma unroll
            for (int p = 0; p < 8; p++) w1p[p] = *(const ulonglong2*)&sW1d[j][p * 2];
#pragma unroll
            for (int c = 0; c < 16; c++) {
                u64 wv = (c & 1) ? w1p[c >> 1].y : w1p[c >> 1].x;
                h0 = fma2(x2[c][0], wv, h0);
                h1 = fma2(x2[c][1], wv, h1);
            }
            float2 ra = up2(h0), rb = up2(h1);
            ra.x = fmaxf(ra.x, 0.f); ra.y = fmaxf(ra.y, 0.f);
            rb.x = fmaxf(rb.x, 0.f); rb.y = fmaxf(rb.y, 0.f);
            u64 r0 = pk2(ra.x, ra.y), r1 = pk2(rb.x, rb.y);
            ulonglong2 w2p[4];
#pragma unroll
            for (int p = 0; p < 4; p++) w2p[p] = *(const ulonglong2*)&sW2d[j][p * 2];
#pragma unroll
            for (int h = 0; h < 8; h++) {
                u64 wv = (h & 1) ? w2p[h >> 1].y : w2p[h >> 1].x;
                f0[h] = fma2(r0, wv, f0[h]);
                f1[h] = fma2(r1, wv, f1[h]);
            }
        }
#pragma unroll
        for (int h = 0; h < 8; h++) {
            ulonglong2 st; st.x = f0[h]; st.y = f1[h];
            *(ulonglong2*)&fs[ql][h][m0] = st;
        }
    }
    __syncthreads();

    const int warp = tid >> 5, lane = tid & 31;
    constexpr int R = QPB * 8;
    for (int row = warp; row < R; row += 8) {
        int qr = row >> 3;
        int hr = row & 7;
        float* frow = fs[qr][hr];
        float mx = -3.0e38f;
        for (int m = lane; m < NK; m += 32) mx = fmaxf(mx, frow[m]);
#pragma unroll
        for (int o = 16; o > 0; o >>= 1) mx = fmaxf(mx, __shfl_xor_sync(0xffffffffu, mx, o));
        float sum = 0.f;
        for (int m = lane; m < NK; m += 32) {
            float ev = __expf(frow[m] - mx);
            frow[m] = ev;
            sum += ev;
        }
#pragma unroll
        for (int o = 16; o > 0; o >>= 1) sum += __shfl_xor_sync(0xffffffffu, sum, o);
        float inv = 1.f / sum;
        size_t base = ((size_t)(hr * Bb + b) * Nq + nb * QPB + qr) * NK;
        for (int m = lane; m < NK; m += 32) {
            float p = frow[m] * inv;
            bf16 h = __float2bfloat16(p);
            Ph[base + m] = h;
            Pl[base + m] = __float2bfloat16(p - __bfloat162float(h));
        }
    }
}

// ================= AV HMMA (V via ldmatrix.trans; split epilogue) =================
struct AVArgs {
    const bf16 *P1h, *P1l, *P2h, *P2l, *P3h, *P3l;
    const bf16 *Vch, *Vcl, *Vsh, *Vsl;    // [(z*TL + t)*32 + e]
    float* heads;
    bf16 *Hhi, *Hlo;
    int which;   // 0 = av1(fp32) + av3(split), 1 = av2 (acc + split)
};
__global__ __launch_bounds__(128) void av_hmma(AVArgs a)
{
    __shared__ __align__(16) bf16 Phs[64][ASTR], Pls[64][ASTR];
    __shared__ __align__(16) bf16 Vhs[32][ASTR], Vls[32][ASTR];
    const int x = blockIdx.x, z = blockIdx.y;
    const int hh = z >> 4, bb = z & 15;
    const bf16 *Ph, *Pl, *Vh, *Vl;
    int Nq, Nk, n0, qoff, mode;   // mode: 0 fp32 store, 1 split store, 2 acc+split
    if (a.which == 0) {
        if (x < 7) { Ph = a.P1h; Pl = a.P1l; Vh = a.Vch; Vl = a.Vcl;
                     Nq = Tt; Nk = Tt; n0 = x * 64; qoff = S1c; mode = 0; }
        else       { Ph = a.P3h; Pl = a.P3l; Vh = a.Vch; Vl = a.Vcl;
                     Nq = S1c; Nk = Tt; n0 = 0; qoff = 0; mode = 1; }
    } else {
        Ph = a.P2h; Pl = a.P2l; Vh = a.Vsh; Vl = a.Vsl;
        Nq = Tt; Nk = S1c; n0 = x * 64; qoff = S1c; mode = 2;
    }
    const int tid = threadIdx.x;
    const int warp = tid >> 5, lane = tid & 31;

    float acc[4][4];
#pragma unroll
    for (int nf = 0; nf < 4; nf++)
#pragma unroll
        for (int j = 0; j < 4; j++) acc[nf][j] = 0.f;

    for (int k0 = 0; k0 < Nk; k0 += 32) {
        if (k0) __syncthreads();
        {
            int rr = tid & 63;
            int sel = tid >> 6;
            int rsw = (rr >> 3) & 3;
            const uint4* ps = (const uint4*)((sel ? Pl : Ph) + ((size_t)z * Nq + n0 + rr) * Nk + k0);
            bf16 (*Pd)[ASTR] = sel ? Pls : Phs;
#pragma unroll
            for (int g = 0; g < 4; g++) {
                int pg = ((g + rsw) & 3) << 3;
                *(uint4*)&Pd[rr][pg] = ps[g];
            }
        }
        if (tid < 64) {
            int rr = tid & 31;          // t row within chunk
            int sel = tid >> 5;
            int rsw = (rr >> 3) & 3;
            const uint4* vs = (const uint4*)((sel ? Vl : Vh) + ((size_t)z * Nk + k0 + rr) * 32);
            bf16 (*Vd)[ASTR] = sel ? Vls : Vhs;
#pragma unroll
            for (int g = 0; g < 4; g++) {
                int pg = ((g + rsw) & 3) << 3;
                *(uint4*)&Vd[rr][pg] = vs[g];
            }
        }
        __syncthreads();
#pragma unroll
        for (int ks = 0; ks < 2; ks++) {
            u32 ah[4], al[4];
            ldA(ah, Phs, warp * 16, ks, lane);
            ldA(al, Pls, warp * 16, ks, lane);
#pragma unroll
            for (int np = 0; np < 2; np++) {
                u32 bh[4], bl[4];
                ldBt(bh, Vhs, np, ks, lane);
                ldBt(bl, Vls, np, ks, lane);
#pragma unroll
                for (int q = 0; q < 2; q++) {
                    int nf = np * 2 + q;
                    mma_bf16(acc[nf], ah, bh[2*q], bh[2*q+1]);
                    mma_bf16(acc[nf], ah, bl[2*q], bl[2*q+1]);
                    mma_bf16(acc[nf], al, bh[2*q], bh[2*q+1]);
                }
            }
        }
    }
#pragma unroll
    for (int nf = 0; nf < 4; nf++) {
        int e = nf * 8 + (lane & 3) * 2;
        int r0 = n0 + warp * 16 + (lane >> 2);
#pragma unroll
        for (int half = 0; half < 2; half++) {
            int rq = r0 + half * 8;
            float2 v = half ? make_float2(acc[nf][2], acc[nf][3])
                            : make_float2(acc[nf][0], acc[nf][1]);
            size_t idx = ((size_t)(bb * Qq + qoff + rq)) * 256 + hh * 32 + e;
            if (mode == 0) {
                *(float2*)(a.heads + idx) = v;
            } else {
                if (mode == 2) {
                    float2 o = *(float2*)(a.heads + idx);
                    v.x += o.x; v.y += o.y;
                }
                split_st(a.Hhi, a.Hlo, idx, v);
            }
        }
    }
}

// ---------------- launch ----------------
extern "C" void kernel_launch(void* const* d_in, const int* in_sizes, int n_in,
                              void* d_out, int out_size)
{
    const float* h_fea      = (const float*)d_in[0];
    const float* aux        = (const float*)d_in[1];
    const float* Wq_custom  = (const float*)d_in[2];
    const float* Wq_custom1 = (const float*)d_in[3];
    const float* Wk_custom  = (const float*)d_in[4];
    const float* Wv_custom  = (const float*)d_in[5];
    const float* Wq_charge1 = (const float*)d_in[6];
    const float* Wk_charge  = (const float*)d_in[7];
    const float* Wv_charge  = (const float*)d_in[8];
    const float* W1         = (const float*)d_in[9];
    const float* b1         = (const float*)d_in[10];
    const float* W2         = (const float*)d_in[11];
    const float* b2         = (const float*)d_in[12];
    const float* W_out      = (const float*)d_in[13];
    float* out = (float*)d_out;

    float *P1, *P2, *P3, *heads;
    bf16 *Xhi, *Xlo, *Hhi, *Hlo, *Wbh, *Wbl;
    bf16 *Q1h, *Q1l, *Q0h, *Q0l, *Kch, *Kcl, *Vch, *Vcl;
    bf16 *Qsh, *Qsl, *Ksh, *Ksl, *Vsh, *Vsl;
    bf16 *P1h, *P1l, *P2h, *P2l, *P3h, *P3l;
    cudaGetSymbolAddress((void**)&P1, g_P1);
    cudaGetSymbolAddress((void**)&P2, g_P2);
    cudaGetSymbolAddress((void**)&P3, g_P3);
    cudaGetSymbolAddress((void**)&heads, g_heads);
    cudaGetSymbolAddress((void**)&Xhi, g_Xhi);
    cudaGetSymbolAddress((void**)&Xlo, g_Xlo);
    cudaGetSymbolAddress((void**)&Hhi, g_Hhi);
    cudaGetSymbolAddress((void**)&Hlo, g_Hlo);
    cudaGetSymbolAddress((void**)&Wbh, g_Wbh);
    cudaGetSymbolAddress((void**)&Wbl, g_Wbl);
    cudaGetSymbolAddress((void**)&Q1h, g_Q1h);  cudaGetSymbolAddress((void**)&Q1l, g_Q1l);
    cudaGetSymbolAddress((void**)&Q0h, g_Q0h);  cudaGetSymbolAddress((void**)&Q0l, g_Q0l);
    cudaGetSymbolAddress((void**)&Kch, g_Kch);  cudaGetSymbolAddress((void**)&Kcl, g_Kcl);
    cudaGetSymbolAddress((void**)&Vch, g_Vch);  cudaGetSymbolAddress((void**)&Vcl, g_Vcl);
    cudaGetSymbolAddress((void**)&Qsh, g_Qsh);  cudaGetSymbolAddress((void**)&Qsl, g_Qsl);
    cudaGetSymbolAddress((void**)&Ksh, g_Ksh);  cudaGetSymbolAddress((void**)&Ksl, g_Ksl);
    cudaGetSymbolAddress((void**)&Vsh, g_Vsh);  cudaGetSymbolAddress((void**)&Vsl, g_Vsl);
    cudaGetSymbolAddress((void**)&P1h, g_P1h);  cudaGetSymbolAddress((void**)&P1l, g_P1l);
    cudaGetSymbolAddress((void**)&P2h, g_P2h);  cudaGetSymbolAddress((void**)&P2l, g_P2l);
    cudaGetSymbolAddress((void**)&P3h, g_P3h);  cudaGetSymbolAddress((void**)&P3l, g_P3l);

    // 1. input/weight splits
    cvt_split_kernel<<<(Bb*Qq*Dd/4 + 255)/256, 256>>>(h_fea, Xhi, Xlo, Bb*Qq*Dd/4);
    WArgs wa;
    wa.W[0] = Wq_custom1; wa.W[1] = Wq_custom; wa.W[2] = Wk_custom; wa.W[3] = Wv_custom;
    wa.W[4] = Wq_charge1; wa.W[5] = Wk_charge; wa.W[6] = Wv_charge; wa.W[7] = W_out;
    cvt_w_kernel<<<8*256*256/256, 256>>>(wa, Wbh, Wbl);

    // 2. merged projections
    HArgs hp;
    hp.Ahi = Xhi; hp.Alo = Xlo; hp.Bh = Wbh; hp.Bl = Wbl;
    hp.Ofp = nullptr; hp.mode = 0;
    hp.Oh[0] = Q1h; hp.Ol[0] = Q1l;
    hp.Oh[1] = Q0h; hp.Ol[1] = Q0l;
    hp.Oh[2] = Kch; hp.Ol[2] = Kcl;
    hp.Oh[3] = Vch; hp.Ol[3] = Vcl;
    hp.Oh[4] = Qsh; hp.Ol[4] = Qsl;
    hp.Oh[5] = Ksh; hp.Ol[5] = Ksl;
    hp.Oh[6] = Vsh; hp.Ol[6] = Vsl;
    hmma_kernel<<<dim3(64, 16), 128>>>(hp);

    // 3. QK^T (all three jobs)
    QKArgs qa;
    qa.Q1h = Q1h; qa.Q1l = Q1l; qa.Q0h = Q0h; qa.Q0l = Q0l; qa.Qsh = Qsh; qa.Qsl = Qsl;
    qa.Kch = Kch; qa.Kcl = Kcl; qa.Ksh = Ksh; qa.Ksl = Ksl;
    qa.P1 = P1; qa.P2 = P2; qa.P3 = P3;
    qk_hmma<<<dim3(63, 128), 128>>>(qa);

    // 4. fuse MLP + softmax -> bf16 split probabilities
    fuse_softmax_kernel<448, 2><<<Bb * (Tt / 2),  256>>>(P1, aux, P1h, P1l, W1, b1, W2, b2, Tt,  S1c, S1c);
    fuse_softmax_kernel<64, 16><<<Bb * (Tt / 16), 256>>>(P2, aux, P2h, P2l, W1, b1, W2, b2, Tt,  S1c, 0);
    fuse_softmax_kernel<448, 2><<<Bb * (S1c / 2), 256>>>(P3, aux, P3h, P3l, W1, b1, W2, b2, S1c, 0,   S1c);

    // 5. AV (V consumed row-major via ldmatrix.trans; epilogues emit head splits)
    AVArgs aa;
    aa.P1h = P1h; aa.P1l = P1l; aa.P2h = P2h; aa.P2l = P2l; aa.P3h = P3h; aa.P3l = P3l;
    aa.Vch = Vch; aa.Vcl = Vcl; aa.Vsh = Vsh; aa.Vsl = Vsl;
    aa.heads = heads; aa.Hhi = Hhi; aa.Hlo = Hlo;
    aa.which = 0;
    av_hmma<<<dim3(8, 128), 128>>>(aa);
    AVArgs ab = aa; ab.which = 1;
    av_hmma<<<dim3(7, 128), 128>>>(ab);

    // 6. output GEMM (reads splits written by av epilogues)
    HArgs ho;
    ho.Ahi = Hhi; ho.Alo = Hlo; ho.Bh = Wbh; ho.Bl = Wbl;
    ho.Ofp = out; ho.mode = 1;
    for (int i = 0; i < 7; i++) { ho.Oh[i] = nullptr; ho.Ol[i] = nullptr; }
    hmma_kernel<<<dim3(64, 4), 128>>>(ho);
}

// round 13
// speedup vs baseline: 1.6140x; 1.0148x over previous
#include <cuda_runtime.h>
#include <cuda_bf16.h>

#define Hh  8
#define Dd  256
#define HDe 32
#define Bb  16
#define Qq  512
#define S1c 64
#define Tt  448

typedef unsigned long long u64;
typedef unsigned int u32;
typedef __nv_bfloat16  bf16;
typedef __nv_bfloat162 bf162;

// ---- packed f32x2 helpers (fuse kernel) ----
__device__ __forceinline__ u64 pk2(float x, float y) {
    u64 r; asm("mov.b64 %0, {%1, %2};" : "=l"(r) : "f"(x), "f"(y)); return r;
}
__device__ __forceinline__ float2 up2(u64 v) {
    float2 r; asm("mov.b64 {%0, %1}, %2;" : "=f"(r.x), "=f"(r.y) : "l"(v)); return r;
}
__device__ __forceinline__ u64 fma2(u64 a, u64 b, u64 c) {
    u64 d; asm("fma.rn.f32x2 %0, %1, %2, %3;" : "=l"(d) : "l"(a), "l"(b), "l"(c)); return d;
}

// ---------------- static scratch ----------------
__device__ float g_P1[128*Tt*Tt];
__device__ float g_P2[128*Tt*S1c];
__device__ float g_P3[128*S1c*Tt];

__device__ bf16 g_Xhi[Bb*Qq*Dd], g_Xlo[Bb*Qq*Dd];
__device__ bf16 g_Hhi[Bb*Qq*Dd], g_Hlo[Bb*Qq*Dd];
__device__ bf16 g_Wbh[8*256*256], g_Wbl[8*256*256];

// proj bf16 splits, layout [(h*16+b)*TL + n]*32 + e
__device__ bf16 g_Q1h[128*Tt*32],  g_Q1l[128*Tt*32];
__device__ bf16 g_Q0h[128*Tt*32],  g_Q0l[128*Tt*32];
__device__ bf16 g_Kch[128*Tt*32],  g_Kcl[128*Tt*32];
__device__ bf16 g_Vch[128*Tt*32],  g_Vcl[128*Tt*32];
__device__ bf16 g_Qsh[128*S1c*32], g_Qsl[128*S1c*32];
__device__ bf16 g_Ksh[128*S1c*32], g_Ksl[128*S1c*32];
__device__ bf16 g_Vsh[128*S1c*32], g_Vsl[128*S1c*32];

// probabilities bf16 splits
__device__ bf16 g_P1h[128*Tt*Tt],  g_P1l[128*Tt*Tt];
__device__ bf16 g_P2h[128*Tt*S1c], g_P2l[128*Tt*S1c];
__device__ bf16 g_P3h[128*S1c*Tt], g_P3l[128*S1c*Tt];

// ================= conversion kernels =================
__global__ __launch_bounds__(256) void cvt_split_kernel(
    const float* __restrict__ src, bf16* __restrict__ hi,
    bf16* __restrict__ lo, int n4)
{
    int i = blockIdx.x * 256 + threadIdx.x;
    if (i >= n4) return;
    float4 v = ((const float4*)src)[i];
    bf16 h0 = __float2bfloat16(v.x), h1 = __float2bfloat16(v.y);
    bf16 h2 = __float2bfloat16(v.z), h3 = __float2bfloat16(v.w);
    ((bf162*)hi)[i*2]   = bf162(h0, h1);
    ((bf162*)hi)[i*2+1] = bf162(h2, h3);
    ((bf162*)lo)[i*2]   = bf162(__float2bfloat16(v.x - __bfloat162float(h0)),
                                __float2bfloat16(v.y - __bfloat162float(h1)));
    ((bf162*)lo)[i*2+1] = bf162(__float2bfloat16(v.z - __bfloat162float(h2)),
                                __float2bfloat16(v.w - __bfloat162float(h3)));
}

struct WArgs { const float* W[8]; };

__global__ __launch_bounds__(256) void cvt_w_kernel(
    WArgs wa, bf16* __restrict__ bh, bf16* __restrict__ bl)
{
    int i = blockIdx.x * 256 + threadIdx.x;
    int s = i >> 16;
    int r = i & 65535;
    int c = r >> 8, k = r & 255;
    const float* W = wa.W[s];
    float x = (s < 7) ? W[(c >> 5) * 8192 + k * 32 + (c & 31)] : W[k * 256 + c];
    bf16 h = __float2bfloat16(x);
    bh[i] = h;
    bl[i] = __float2bfloat16(x - __bfloat162float(h));
}

// ================= shared HMMA machinery =================
#define ASTR 40

__device__ __forceinline__ u32 smaddr(const void* p) {
    return (u32)__cvta_generic_to_shared(p);
}
__device__ __forceinline__ void ldsm4(u32& r0, u32& r1, u32& r2, u32& r3, u32 a) {
    asm volatile("ldmatrix.sync.aligned.m8n8.x4.shared.b16 {%0,%1,%2,%3},[%4];"
        : "=r"(r0), "=r"(r1), "=r"(r2), "=r"(r3) : "r"(a));
}
__device__ __forceinline__ void ldsm4t(u32& r0, u32& r1, u32& r2, u32& r3, u32 a) {
    asm volatile("ldmatrix.sync.aligned.m8n8.x4.trans.shared.b16 {%0,%1,%2,%3},[%4];"
        : "=r"(r0), "=r"(r1), "=r"(r2), "=r"(r3) : "r"(a));
}

__device__ __forceinline__ void ldA(u32* a, const bf16 (*M)[ASTR], int R0, int ks, int lane) {
    int row = R0 + ((lane >> 3) & 1) * 8 + (lane & 7);
    int kg  = 2 * ks + (lane >> 4);
    ldsm4(a[0], a[1], a[2], a[3], smaddr(&M[row][((kg + (row >> 3)) & 3) << 3]));
}
__device__ __forceinline__ void ldB(u32* b, const bf16 (*M)[ASTR], int N0, int ks, int lane) {
    int row = N0 + (lane >> 4) * 8 + (lane & 7);
    int kg  = 2 * ks + ((lane >> 3) & 1);
    ldsm4(b[0], b[1], b[2], b[3], smaddr(&M[row][((kg + (row >> 3)) & 3) << 3]));
}
__device__ __forceinline__ void ldBt(u32* b, const bf16 (*M)[ASTR], int nfp, int ks, int lane) {
    int row = ks * 16 + ((lane >> 3) & 1) * 8 + (lane & 7);
    int eg  = nfp * 2 + (lane >> 4);
    ldsm4t(b[0], b[1], b[2], b[3], smaddr(&M[row][((eg + (row >> 3)) & 3) << 3]));
}

__device__ __forceinline__ void mma_bf16(float* d, const u32* a, u32 b0, u32 b1) {
    asm volatile(
        "mma.sync.aligned.m16n8k16.row.col.f32.bf16.bf16.f32 "
        "{%0,%1,%2,%3}, {%4,%5,%6,%7}, {%8,%9}, {%0,%1,%2,%3};"
        : "+f"(d[0]), "+f"(d[1]), "+f"(d[2]), "+f"(d[3])
        : "r"(a[0]), "r"(a[1]), "r"(a[2]), "r"(a[3]), "r"(b0), "r"(b1));
}

__device__ __forceinline__ void split_st(bf16* hp, bf16* lp, size_t idx, float2 v) {
    bf16 h0 = __float2bfloat16(v.x), h1 = __float2bfloat16(v.y);
    *(bf162*)(hp + idx) = bf162(h0, h1);
    *(bf162*)(lp + idx) = bf162(__float2bfloat16(v.x - __bfloat162float(h0)),
                                __float2bfloat16(v.y - __bfloat162float(h1)));
}

// fill one 64-row tile (hi or lo selected by sel) from [(rowbase+rr)*32] source
__device__ __forceinline__ void fill_tile(
    bf16 (*Dh)[ASTR], bf16 (*Dl)[ASTR],
    const bf16* __restrict__ srcH, const bf16* __restrict__ srcL,
    size_t rowbase, int rr, int sel, int rsw)
{
    const uint4* s = (const uint4*)((sel ? srcL : srcH) + (rowbase + rr) * 32);
    bf16 (*D)[ASTR] = sel ? Dl : Dh;
#pragma unroll
    for (int g = 0; g < 4; g++) {
        int pg = ((g + rsw) & 3) << 3;
        *(uint4*)&D[rr][pg] = s[g];
    }
}

// ================= proj/out HMMA kernel =================
struct HArgs {
    const bf16 *Ahi, *Alo;
    const bf16 *Bh, *Bl;
    float* Ofp;
    bf16 *Oh[7], *Ol[7];
    int mode;
};

__global__ __launch_bounds__(128) void hmma_kernel(HArgs args)
{
    __shared__ __align__(16) bf16 Ah[128][ASTR], Al[128][ASTR];
    __shared__ __align__(16) bf16 Bhs[64][ASTR], Bls[64][ASTR];
    const int x = blockIdx.x, y = blockIdx.y;
    int set, col0, TL, qoff, m0;
    if (args.mode == 0) {
        if (x < 56) { set = y >> 2; col0 = (y & 3) * 64; TL = Tt; qoff = S1c; m0 = x * 128; }
        else {
            if (y >= 12) return;
            set = 4 + (y >> 2); col0 = (y & 3) * 64; TL = S1c; qoff = 0; m0 = (x - 56) * 128;
        }
    } else { set = 7; col0 = y * 64; TL = Qq; qoff = 0; m0 = x * 128; }

    const int tid = threadIdx.x;
    const int warp = tid >> 5, lane = tid & 31;

    float acc[2][8][4];
#pragma unroll
    for (int mf = 0; mf < 2; mf++)
#pragma unroll
        for (int nf = 0; nf < 8; nf++)
#pragma unroll
            for (int j = 0; j < 4; j++) acc[mf][nf][j] = 0.f;

    int t = m0 + tid;
    int ab = t / TL;
    size_t arow = ((size_t)ab * Qq + qoff + (t - ab * TL)) * 256;
    const int br = tid & 63;
    const bf16* Bsrc = ((tid < 64) ? args.Bh : args.Bl) + (size_t)set * 65536 + (size_t)(col0 + br) * 256;
    const int rswA = (tid >> 3) & 3;
    const int rswB = (br >> 3) & 3;

    for (int k0 = 0; k0 < 256; k0 += 32) {
        if (k0) __syncthreads();
        const uint4* sAh = (const uint4*)(args.Ahi + arow + k0);
        const uint4* sAl = (const uint4*)(args.Alo + arow + k0);
#pragma unroll
        for (int g = 0; g < 4; g++) {
            int pg = ((g + rswA) & 3) << 3;
            *(uint4*)&Ah[tid][pg] = sAh[g];
            *(uint4*)&Al[tid][pg] = sAl[g];
        }
        {
            const uint4* sB = (const uint4*)(Bsrc + k0);
            bf16 (*Bd)[ASTR] = (tid < 64) ? Bhs : Bls;
#pragma unroll
            for (int g = 0; g < 4; g++) {
                int pg = ((g + rswB) & 3) << 3;
                *(uint4*)&Bd[br][pg] = sB[g];
            }
        }
        __syncthreads();
#pragma unroll
        for (int ks = 0; ks < 2; ks++) {
            u32 ah[2][4], al[2][4];
            ldA(ah[0], Ah, warp * 32,      ks, lane);
            ldA(ah[1], Ah, warp * 32 + 16, ks, lane);
            ldA(al[0], Al, warp * 32,      ks, lane);
            ldA(al[1], Al, warp * 32 + 16, ks, lane);
#pragma unroll
            for (int np = 0; np < 4; np++) {
                u32 bh[4], bl[4];
                ldB(bh, Bhs, np * 16, ks, lane);
                ldB(bl, Bls, np * 16, ks, lane);
#pragma unroll
                for (int q = 0; q < 2; q++) {
                    int nf = np * 2 + q;
#pragma unroll
                    for (int mf = 0; mf < 2; mf++) {
                        mma_bf16(acc[mf][nf], ah[mf], bh[2*q], bh[2*q+1]);
                        mma_bf16(acc[mf][nf], ah[mf], bl[2*q], bl[2*q+1]);
                        mma_bf16(acc[mf][nf], al[mf], bh[2*q], bh[2*q+1]);
                    }
                }
            }
        }
    }

#pragma unroll
    for (int mf = 0; mf < 2; mf++) {
#pragma unroll
        for (int nf = 0; nf < 8; nf++) {
            int lc = nf * 8 + (lane & 3) * 2;
            int t0 = m0 + warp * 32 + mf * 16 + (lane >> 2);
            int t1 = t0 + 8;
            float2 v0 = make_float2(acc[mf][nf][0], acc[mf][nf][1]);
            float2 v1 = make_float2(acc[mf][nf][2], acc[mf][nf][3]);
            if (args.mode == 0) {
                int c = col0 + lc;
                int h = c >> 5, e = c & 31;
                int b0i = t0 / TL, n0i = t0 - b0i * TL;
                int b1i = t1 / TL, n1i = t1 - b1i * TL;
                size_t i0 = (((size_t)h * Bb + b0i) * TL + n0i) * 32 + e;
                size_t i1 = (((size_t)h * Bb + b1i) * TL + n1i) * 32 + e;
                split_st(args.Oh[set], args.Ol[set], i0, v0);
                split_st(args.Oh[set], args.Ol[set], i1, v1);
            } else {
                int d = col0 + lc;
                *(float2*)(args.Ofp + (size_t)t0 * 256 + d) = v0;
                *(float2*)(args.Ofp + (size_t)t1 * 256 + d) = v1;
            }
        }
    }
}

// ================= QK^T HMMA (stationary-tile loop version) =================
struct QKArgs {
    const bf16 *Q1h, *Q1l, *Q0h, *Q0l, *Qsh, *Qsl;
    const bf16 *Kch, *Kcl, *Ksh, *Ksl;
    float *P1, *P2, *P3;
};

// compute one 64x64 S tile from Q/K smem and store fp32
__device__ __forceinline__ void qk_tile(
    const bf16 (*Qhs)[ASTR], const bf16 (*Qls)[ASTR],
    const bf16 (*Khs)[ASTR], const bf16 (*Kls)[ASTR],
    float* Sb, int Nk, int row0, int col0, int warp, int lane)
{
    float acc[8][4];
#pragma unroll
    for (int nf = 0; nf < 8; nf++)
#pragma unroll
        for (int j = 0; j < 4; j++) acc[nf][j] = 0.f;
#pragma unroll
    for (int ks = 0; ks < 2; ks++) {
        u32 ah[4], al[4];
        ldA(ah, Qhs, warp * 16, ks, lane);
        ldA(al, Qls, warp * 16, ks, lane);
#pragma unroll
        for (int np = 0; np < 4; np++) {
            u32 bh[4], bl[4];
            ldB(bh, Khs, np * 16, ks, lane);
            ldB(bl, Kls, np * 16, ks, lane);
#pragma unroll
            for (int q = 0; q < 2; q++) {
                int nf = np * 2 + q;
                mma_bf16(acc[nf], ah, bh[2*q], bh[2*q+1]);
                mma_bf16(acc[nf], ah, bl[2*q], bl[2*q+1]);
                mma_bf16(acc[nf], al, bh[2*q], bh[2*q+1]);
            }
        }
    }
#pragma unroll
    for (int nf = 0; nf < 8; nf++) {
        int col = col0 + nf * 8 + (lane & 3) * 2;
        int r0 = row0 + warp * 16 + (lane >> 2);
        *(float2*)(Sb + (size_t)r0 * Nk + col)       = make_float2(acc[nf][0], acc[nf][1]);
        *(float2*)(Sb + (size_t)(r0 + 8) * Nk + col) = make_float2(acc[nf][2], acc[nf][3]);
    }
}

__global__ __launch_bounds__(128) void qk_hmma(QKArgs a)
{
    __shared__ __align__(16) bf16 Qhs[64][ASTR], Qls[64][ASTR];
    __shared__ __align__(16) bf16 Khs[64][ASTR], Kls[64][ASTR];
    const int x = blockIdx.x, z = blockIdx.y;
    const int tid = threadIdx.x;
    const int warp = tid >> 5, lane = tid & 31;
    const int rr = tid & 63;
    const int sel = tid >> 6;
    const int rsw = (rr >> 3) & 3;

    if (x < 7) {
        // job1: stationary Q1 tile x, loop 7 Kc tiles
        fill_tile(Qhs, Qls, a.Q1h, a.Q1l, (size_t)z * Tt + x * 64, rr, sel, rsw);
        float* Sb = a.P1 + (size_t)z * Tt * Tt;
        for (int mt = 0; mt < 7; mt++) {
            if (mt) __syncthreads();
            fill_tile(Khs, Kls, a.Kch, a.Kcl, (size_t)z * Tt + mt * 64, rr, sel, rsw);
            __syncthreads();
            qk_tile(Qhs, Qls, Khs, Kls, Sb, Tt, x * 64, mt * 64, warp, lane);
        }
    } else if (x == 7) {
        // job2: stationary Ks, loop 7 Q0 tiles
        fill_tile(Khs, Kls, a.Ksh, a.Ksl, (size_t)z * S1c, rr, sel, rsw);
        float* Sb = a.P2 + (size_t)z * Tt * S1c;
        for (int qt = 0; qt < 7; qt++) {
            if (qt) __syncthreads();
            fill_tile(Qhs, Qls, a.Q0h, a.Q0l, (size_t)z * Tt + qt * 64, rr, sel, rsw);
            __syncthreads();
            qk_tile(Qhs, Qls, Khs, Kls, Sb, S1c, qt * 64, 0, warp, lane);
        }
    } else {
        // job3: stationary Qs, loop 7 Kc tiles
        fill_tile(Qhs, Qls, a.Qsh, a.Qsl, (size_t)z * S1c, rr, sel, rsw);
        float* Sb = a.P3 + (size_t)z * S1c * Tt;
        for (int mt = 0; mt < 7; mt++) {
            if (mt) __syncthreads();
            fill_tile(Khs, Kls, a.Kch, a.Kcl, (size_t)z * Tt + mt * 64, rr, sel, rsw);
            __syncthreads();
            qk_tile(Qhs, Qls, Khs, Kls, Sb, Tt, 0, mt * 64, warp, lane);
        }
    }
}

// ================= fuse MLP + softmax (bf16 split output) =================
template<int NK, int QPB>
__global__ __launch_bounds__(256) void fuse_softmax_kernel(
    const float* __restrict__ S, const float* __restrict__ aux,
    bf16* __restrict__ Ph, bf16* __restrict__ Pl,
    const float* __restrict__ W1, const float* __restrict__ b1,
    const float* __restrict__ W2, const float* __restrict__ b2,
    int Nq, int qn_off, int qm_off)
{
    __shared__ __align__(16) u64 sW1d[16][16];
    __shared__ __align__(16) u64 sW2d[16][8];
    __shared__ u64 sb1d[16], sb2d[8];
    __shared__ __align__(16) float fs[QPB][8][NK];
    const int tid = threadIdx.x;
    { int j = tid >> 4, c = tid & 15; float w = W1[c * 16 + j]; sW1d[j][c] = pk2(w, w); }
    if (tid < 128) { int j = tid >> 3, h = tid & 7; float w = W2[j * 8 + h]; sW2d[j][h] = pk2(w, w); }
    if (tid < 16)  { float w = b1[tid]; sb1d[tid] = pk2(w, w); }
    if (tid < 8)   { float w = b2[tid]; sb2d[tid] = pk2(w, w); }
    __syncthreads();

    const int nblocks = Nq / QPB;
    const int nb = blockIdx.x % nblocks;
    const int b  = blockIdx.x / nblocks;
    constexpr int TPQ = 256 / QPB;
    const int ql = tid / TPQ;
    const int tl = tid % TPQ;
    const int n  = nb * QPB + ql;
    const int m0 = tl * 4;

    if (m0 < NK) {
        u64 x2[16][2];
#pragma unroll
        for (int h = 0; h < 8; h++) {
            ulonglong2 v = *(const ulonglong2*)(S + ((size_t)(h * Bb + b) * Nq + n) * NK + m0);
            x2[h][0] = v.x; x2[h][1] = v.y;
            ulonglong2 w = *(const ulonglong2*)(aux + ((size_t)(h * Bb + b) * Qq + qn_off + n) * Qq + qm_off + m0);
            x2[8 + h][0] = w.x; x2[8 + h][1] = w.y;
        }
        u64 f0[8], f1[8];
#pragma unroll
        for (int h = 0; h < 8; h++) { f0[h] = sb2d[h]; f1[h] = f0[h]; }
#pragma unroll
        for (int j = 0; j < 16; j++) {
            u64 h0 = sb1d[j], h1 = h0;
            ulonglong2 w1p[8];
#pragma unroll
            for (int p = 0; p < 8; p++) w1p[p] = *(const ulonglong2*)&sW1d[j][p * 2];
#pragma unroll
            for (int c = 0; c < 16; c++) {
                u64 wv = (c & 1) ? w1p[c >> 1].y : w1p[c >> 1].x;
                h0 = fma2(x2[c][0], wv, h0);
                h1 = fma2(x2[c][1], wv, h1);
            }
            float2 ra = up2(h0), rb = up2(h1);
            ra.x = fmaxf(ra.x, 0.f); ra.y = fmaxf(ra.y, 0.f);
            rb.x = fmaxf(rb.x, 0.f); rb.y = fmaxf(rb.y, 0.f);
            u64 r0 = pk2(ra.x, ra.y), r1 = pk2(rb.x, rb.y);
            ulonglong2 w2p[4];
#pragma unroll
            for (int p = 0; p < 4; p++) w2p[p] = *(const ulonglong2*)&sW2d[j][p * 2];
#pragma unroll
            for (int h = 0; h < 8; h++) {
                u64 wv = (h & 1) ? w2p[h >> 1].y : w2p[h >> 1].x;
                f0[h] = fma2(r0, wv, f0[h]);
                f1[h] = fma2(r1, wv, f1[h]);
            }
        }
#pragma unroll
        for (int h = 0; h < 8; h++) {
            ulonglong2 st; st.x = f0[h]; st.y = f1[h];
            *(ulonglong2*)&fs[ql][h][m0] = st;
        }
    }
    __syncthreads();

    const int warp = tid >> 5, lane = tid & 31;
    constexpr int R = QPB * 8;
    for (int row = warp; row < R; row += 8) {
        int qr = row >> 3;
        int hr = row & 7;
        float* frow = fs[qr][hr];
        float mx = -3.0e38f;
        for (int m = lane; m < NK; m += 32) mx = fmaxf(mx, frow[m]);
#pragma unroll
        for (int o = 16; o > 0; o >>= 1) mx = fmaxf(mx, __shfl_xor_sync(0xffffffffu, mx, o));
        float sum = 0.f;
        for (int m = lane; m < NK; m += 32) {
            float ev = __expf(frow[m] - mx);
            frow[m] = ev;
            sum += ev;
        }
#pragma unroll
        for (int o = 16; o > 0; o >>= 1) sum += __shfl_xor_sync(0xffffffffu, sum, o);
        float inv = 1.f / sum;
        size_t base = ((size_t)(hr * Bb + b) * Nq + nb * QPB + qr) * NK;
        for (int m = lane; m < NK; m += 32) {
            float p = frow[m] * inv;
            bf16 h = __float2bfloat16(p);
            Ph[base + m] = h;
            Pl[base + m] = __float2bfloat16(p - __bfloat162float(h));
        }
    }
}

// ================= merged AV HMMA (single launch, split epilogue) =================
struct AVArgs {
    const bf16 *P1h, *P1l, *P2h, *P2l, *P3h, *P3l;
    const bf16 *Vch, *Vcl, *Vsh, *Vsl;
    bf16 *Hhi, *Hlo;
};
__global__ __launch_bounds__(128) void av_hmma(AVArgs a)
{
    __shared__ __align__(16) bf16 Phs[64][ASTR], Pls[64][ASTR];
    __shared__ __align__(16) bf16 Vhs[32][ASTR], Vls[32][ASTR];
    const int x = blockIdx.x, z = blockIdx.y;
    const int hh = z >> 4, bb = z & 15;
    const int tid = threadIdx.x;
    const int warp = tid >> 5, lane = tid & 31;

    int n0, qoff, nchunks;
    if (x < 7) { n0 = x * 64; qoff = S1c; nchunks = 16; }  // task rows: P1*Vc (14) + P2*Vs (2)
    else       { n0 = 0;      qoff = 0;   nchunks = 14; }  // stat rows: P3*Vc

    float acc[4][4];
#pragma unroll
    for (int nf = 0; nf < 4; nf++)
#pragma unroll
        for (int j = 0; j < 4; j++) acc[nf][j] = 0.f;

    for (int c = 0; c < nchunks; c++) {
        if (c) __syncthreads();
        const bf16 *Ph, *Pl, *Vh, *Vl;
        size_t prow; int pstride; size_t vrow;
        if (x < 7) {
            if (c < 14) {
                Ph = a.P1h; Pl = a.P1l; Vh = a.Vch; Vl = a.Vcl;
                pstride = Tt;  prow = ((size_t)z * Tt + n0) * Tt + c * 32;
                vrow = (size_t)z * Tt + c * 32;
            } else {
                Ph = a.P2h; Pl = a.P2l; Vh = a.Vsh; Vl = a.Vsl;
                pstride = S1c; prow = ((size_t)z * Tt + n0) * S1c + (c - 14) * 32;
                vrow = (size_t)z * S1c + (c - 14) * 32;
            }
        } else {
            Ph = a.P3h; Pl = a.P3l; Vh = a.Vch; Vl = a.Vcl;
            pstride = Tt;  prow = ((size_t)z * S1c) * Tt + c * 32;
            vrow = (size_t)z * Tt + c * 32;
        }
        {
            int rr = tid & 63;
            int sel = tid >> 6;
            int rsw = (rr >> 3) & 3;
            const uint4* ps = (const uint4*)((sel ? Pl : Ph) + prow + (size_t)rr * pstride);
            bf16 (*Pd)[ASTR] = sel ? Pls : Phs;
#pragma unroll
            for (int g = 0; g < 4; g++) {
                int pg = ((g + rsw) & 3) << 3;
                *(uint4*)&Pd[rr][pg] = ps[g];
            }
        }
        if (tid < 64) {
            int rr = tid & 31;
            int sel = tid >> 5;
            int rsw = (rr >> 3) & 3;
            const uint4* vs = (const uint4*)((sel ? Vl : Vh) + (vrow + rr) * 32);
            bf16 (*Vd)[ASTR] = sel ? Vls : Vhs;
#pragma unroll
            for (int g = 0; g < 4; g++) {
                int pg = ((g + rsw) & 3) << 3;
                *(uint4*)&Vd[rr][pg] = vs[g];
            }
        }
        __syncthreads();
#pragma unroll
        for (int ks = 0; ks < 2; ks++) {
            u32 ah[4], al[4];
            ldA(ah, Phs, warp * 16, ks, lane);
            ldA(al, Pls, warp * 16, ks, lane);
#pragma unroll
            for (int np = 0; np < 2; np++) {
                u32 bh[4], bl[4];
                ldBt(bh, Vhs, np, ks, lane);
                ldBt(bl, Vls, np, ks, lane);
#pragma unroll
                for (int q = 0; q < 2; q++) {
                    int nf = np * 2 + q;
                    mma_bf16(acc[nf], ah, bh[2*q], bh[2*q+1]);
                    mma_bf16(acc[nf], ah, bl[2*q], bl[2*q+1]);
                    mma_bf16(acc[nf], al, bh[2*q], bh[2*q+1]);
                }
            }
        }
    }
#pragma unroll
    for (int nf = 0; nf < 4; nf++) {
        int e = nf * 8 + (lane & 3) * 2;
        int r0 = n0 + warp * 16 + (lane >> 2);
#pragma unroll
        for (int half = 0; half < 2; half++) {
            int rq = r0 + half * 8;
            float2 v = half ? make_float2(acc[nf][2], acc[nf][3])
                            : make_float2(acc[nf][0], acc[nf][1]);
            size_t idx = ((size_t)(bb * Qq + qoff + rq)) * 256 + hh * 32 + e;
            split_st(a.Hhi, a.Hlo, idx, v);
        }
    }
}

// ---------------- launch ----------------
extern "C" void kernel_launch(void* const* d_in, const int* in_sizes, int n_in,
                              void* d_out, int out_size)
{
    const float* h_fea      = (const float*)d_in[0];
    const float* aux        = (const float*)d_in[1];
    const float* Wq_custom  = (const float*)d_in[2];
    const float* Wq_custom1 = (const float*)d_in[3];
    const float* Wk_custom  = (const float*)d_in[4];
    const float* Wv_custom  = (const float*)d_in[5];
    const float* Wq_charge1 = (const float*)d_in[6];
    const float* Wk_charge  = (const float*)d_in[7];
    const float* Wv_charge  = (const float*)d_in[8];
    const float* W1         = (const float*)d_in[9];
    const float* b1         = (const float*)d_in[10];
    const float* W2         = (const float*)d_in[11];
    const float* b2         = (const float*)d_in[12];
    const float* W_out      = (const float*)d_in[13];
    float* out = (float*)d_out;

    float *P1, *P2, *P3;
    bf16 *Xhi, *Xlo, *Hhi, *Hlo, *Wbh, *Wbl;
    bf16 *Q1h, *Q1l, *Q0h, *Q0l, *Kch, *Kcl, *Vch, *Vcl;
    bf16 *Qsh, *Qsl, *Ksh, *Ksl, *Vsh, *Vsl;
    bf16 *P1h, *P1l, *P2h, *P2l, *P3h, *P3l;
    cudaGetSymbolAddress((void**)&P1, g_P1);
    cudaGetSymbolAddress((void**)&P2, g_P2);
    cudaGetSymbolAddress((void**)&P3, g_P3);
    cudaGetSymbolAddress((void**)&Xhi, g_Xhi);
    cudaGetSymbolAddress((void**)&Xlo, g_Xlo);
    cudaGetSymbolAddress((void**)&Hhi, g_Hhi);
    cudaGetSymbolAddress((void**)&Hlo, g_Hlo);
    cudaGetSymbolAddress((void**)&Wbh, g_Wbh);
    cudaGetSymbolAddress((void**)&Wbl, g_Wbl);
    cudaGetSymbolAddress((void**)&Q1h, g_Q1h);  cudaGetSymbolAddress((void**)&Q1l, g_Q1l);
    cudaGetSymbolAddress((void**)&Q0h, g_Q0h);  cudaGetSymbolAddress((void**)&Q0l, g_Q0l);
    cudaGetSymbolAddress((void**)&Kch, g_Kch);  cudaGetSymbolAddress((void**)&Kcl, g_Kcl);
    cudaGetSymbolAddress((void**)&Vch, g_Vch);  cudaGetSymbolAddress((void**)&Vcl, g_Vcl);
    cudaGetSymbolAddress((void**)&Qsh, g_Qsh);  cudaGetSymbolAddress((void**)&Qsl, g_Qsl);
    cudaGetSymbolAddress((void**)&Ksh, g_Ksh);  cudaGetSymbolAddress((void**)&Ksl, g_Ksl);
    cudaGetSymbolAddress((void**)&Vsh, g_Vsh);  cudaGetSymbolAddress((void**)&Vsl, g_Vsl);
    cudaGetSymbolAddress((void**)&P1h, g_P1h);  cudaGetSymbolAddress((void**)&P1l, g_P1l);
    cudaGetSymbolAddress((void**)&P2h, g_P2h);  cudaGetSymbolAddress((void**)&P2l, g_P2l);
    cudaGetSymbolAddress((void**)&P3h, g_P3h);  cudaGetSymbolAddress((void**)&P3l, g_P3l);

    // 1. input/weight splits
    cvt_split_kernel<<<(Bb*Qq*Dd/4 + 255)/256, 256>>>(h_fea, Xhi, Xlo, Bb*Qq*Dd/4);
    WArgs wa;
    wa.W[0] = Wq_custom1; wa.W[1] = Wq_custom; wa.W[2] = Wk_custom; wa.W[3] = Wv_custom;
    wa.W[4] = Wq_charge1; wa.W[5] = Wk_charge; wa.W[6] = Wv_charge; wa.W[7] = W_out;
    cvt_w_kernel<<<8*256*256/256, 256>>>(wa, Wbh, Wbl);

    // 2. merged projections
    HArgs hp;
    hp.Ahi = Xhi; hp.Alo = Xlo; hp.Bh = Wbh; hp.Bl = Wbl;
    hp.Ofp = nullptr; hp.mode = 0;
    hp.Oh[0] = Q1h; hp.Ol[0] = Q1l;
    hp.Oh[1] = Q0h; hp.Ol[1] = Q0l;
    hp.Oh[2] = Kch; hp.Ol[2] = Kcl;
    hp.Oh[3] = Vch; hp.Ol[3] = Vcl;
    hp.Oh[4] = Qsh; hp.Ol[4] = Qsl;
    hp.Oh[5] = Ksh; hp.Ol[5] = Ksl;
    hp.Oh[6] = Vsh; hp.Ol[6] = Vsl;
    hmma_kernel<<<dim3(64, 16), 128>>>(hp);

    // 3. QK^T (stationary-tile loops, 9 jobs x 128 z)
    QKArgs qa;
    qa.Q1h = Q1h; qa.Q1l = Q1l; qa.Q0h = Q0h; qa.Q0l = Q0l; qa.Qsh = Qsh; qa.Qsl = Qsl;
    qa.Kch = Kch; qa.Kcl = Kcl; qa.Ksh = Ksh; qa.Ksl = Ksl;
    qa.P1 = P1; qa.P2 = P2; qa.P3 = P3;
    qk_hmma<<<dim3(9, 128), 128>>>(qa);

    // 4. fuse MLP + softmax -> bf16 split probabilities
    fuse_softmax_kernel<448, 2><<<Bb * (Tt / 2),  256>>>(P1, aux, P1h, P1l, W1, b1, W2, b2, Tt,  S1c, S1c);
    fuse_softmax_kernel<64, 16><<<Bb * (Tt / 16), 256>>>(P2, aux, P2h, P2l, W1, b1, W2, b2, Tt,  S1c, 0);
    fuse_softmax_kernel<448, 2><<<Bb * (S1c / 2), 256>>>(P3, aux, P3h, P3l, W1, b1, W2, b2, S1c, 0,   S1c);

    // 5. merged AV (av1+av2 fused in-block; av3 alongside) -> head splits directly
    AVArgs aa;
    aa.P1h = P1h; aa.P1l = P1l; aa.P2h = P2h; aa.P2l = P2l; aa.P3h = P3h; aa.P3l = P3l;
    aa.Vch = Vch; aa.Vcl = Vcl; aa.Vsh = Vsh; aa.Vsl = Vsl;
    aa.Hhi = Hhi; aa.Hlo = Hlo;
    av_hmma<<<dim3(8, 128), 128>>>(aa);

    // 6. output GEMM (reads splits written by av epilogues)
    HArgs ho;
    ho.Ahi = Hhi; ho.Alo = Hlo; ho.Bh = Wbh; ho.Bl = Wbl;
    ho.Ofp = out; ho.mode = 1;
    for (int i = 0; i < 7; i++) { ho.Oh[i] = nullptr; ho.Ol[i] = nullptr; }
    hmma_kernel<<<dim3(64, 4), 128>>>(ho);
}

// round 14
// speedup vs baseline: 1.9905x; 1.2333x over previous
#include <cuda_runtime.h>
#include <cuda_bf16.h>

#define Hh  8
#define Dd  256
#define HDe 32
#define Bb  16
#define Qq  512
#define S1c 64
#define Tt  448

typedef unsigned long long u64;
typedef unsigned int u32;
typedef __nv_bfloat16  bf16;
typedef __nv_bfloat162 bf162;

// ---------------- static scratch ----------------
__device__ float g_P1[128*Tt*Tt];
__device__ float g_P2[128*Tt*S1c];
__device__ float g_P3[128*S1c*Tt];

__device__ bf16 g_Xhi[Bb*Qq*Dd], g_Xlo[Bb*Qq*Dd];
__device__ bf16 g_Hhi[Bb*Qq*Dd], g_Hlo[Bb*Qq*Dd];
__device__ bf16 g_Wbh[8*256*256], g_Wbl[8*256*256];

__device__ bf16 g_Q1h[128*Tt*32],  g_Q1l[128*Tt*32];
__device__ bf16 g_Q0h[128*Tt*32],  g_Q0l[128*Tt*32];
__device__ bf16 g_Kch[128*Tt*32],  g_Kcl[128*Tt*32];
__device__ bf16 g_Vch[128*Tt*32],  g_Vcl[128*Tt*32];
__device__ bf16 g_Qsh[128*S1c*32], g_Qsl[128*S1c*32];
__device__ bf16 g_Ksh[128*S1c*32], g_Ksl[128*S1c*32];
__device__ bf16 g_Vsh[128*S1c*32], g_Vsl[128*S1c*32];

__device__ bf16 g_P1h[128*Tt*Tt],  g_P1l[128*Tt*Tt];
__device__ bf16 g_P2h[128*Tt*S1c], g_P2l[128*Tt*S1c];
__device__ bf16 g_P3h[128*S1c*Tt], g_P3l[128*S1c*Tt];

// ================= conversion kernels =================
__global__ __launch_bounds__(256) void cvt_split_kernel(
    const float* __restrict__ src, bf16* __restrict__ hi,
    bf16* __restrict__ lo, int n4)
{
    int i = blockIdx.x * 256 + threadIdx.x;
    if (i >= n4) return;
    float4 v = ((const float4*)src)[i];
    bf16 h0 = __float2bfloat16(v.x), h1 = __float2bfloat16(v.y);
    bf16 h2 = __float2bfloat16(v.z), h3 = __float2bfloat16(v.w);
    ((bf162*)hi)[i*2]   = bf162(h0, h1);
    ((bf162*)hi)[i*2+1] = bf162(h2, h3);
    ((bf162*)lo)[i*2]   = bf162(__float2bfloat16(v.x - __bfloat162float(h0)),
                                __float2bfloat16(v.y - __bfloat162float(h1)));
    ((bf162*)lo)[i*2+1] = bf162(__float2bfloat16(v.z - __bfloat162float(h2)),
                                __float2bfloat16(v.w - __bfloat162float(h3)));
}

struct WArgs { const float* W[8]; };

__global__ __launch_bounds__(256) void cvt_w_kernel(
    WArgs wa, bf16* __restrict__ bh, bf16* __restrict__ bl)
{
    int i = blockIdx.x * 256 + threadIdx.x;
    int s = i >> 16;
    int r = i & 65535;
    int c = r >> 8, k = r & 255;
    const float* W = wa.W[s];
    float x = (s < 7) ? W[(c >> 5) * 8192 + k * 32 + (c & 31)] : W[k * 256 + c];
    bf16 h = __float2bfloat16(x);
    bh[i] = h;
    bl[i] = __float2bfloat16(x - __bfloat162float(h));
}

// ================= shared HMMA machinery =================
#define ASTR 40

__device__ __forceinline__ u32 smaddr(const void* p) {
    return (u32)__cvta_generic_to_shared(p);
}
__device__ __forceinline__ void ldsm4(u32& r0, u32& r1, u32& r2, u32& r3, u32 a) {
    asm volatile("ldmatrix.sync.aligned.m8n8.x4.shared.b16 {%0,%1,%2,%3},[%4];"
        : "=r"(r0), "=r"(r1), "=r"(r2), "=r"(r3) : "r"(a));
}
__device__ __forceinline__ void ldsm4t(u32& r0, u32& r1, u32& r2, u32& r3, u32 a) {
    asm volatile("ldmatrix.sync.aligned.m8n8.x4.trans.shared.b16 {%0,%1,%2,%3},[%4];"
        : "=r"(r0), "=r"(r1), "=r"(r2), "=r"(r3) : "r"(a));
}

__device__ __forceinline__ void ldA(u32* a, const bf16 (*M)[ASTR], int R0, int ks, int lane) {
    int row = R0 + ((lane >> 3) & 1) * 8 + (lane & 7);
    int kg  = 2 * ks + (lane >> 4);
    ldsm4(a[0], a[1], a[2], a[3], smaddr(&M[row][((kg + (row >> 3)) & 3) << 3]));
}
__device__ __forceinline__ void ldB(u32* b, const bf16 (*M)[ASTR], int N0, int ks, int lane) {
    int row = N0 + (lane >> 4) * 8 + (lane & 7);
    int kg  = 2 * ks + ((lane >> 3) & 1);
    ldsm4(b[0], b[1], b[2], b[3], smaddr(&M[row][((kg + (row >> 3)) & 3) << 3]));
}
__device__ __forceinline__ void ldBt(u32* b, const bf16 (*M)[ASTR], int nfp, int ks, int lane) {
    int row = ks * 16 + ((lane >> 3) & 1) * 8 + (lane & 7);
    int eg  = nfp * 2 + (lane >> 4);
    ldsm4t(b[0], b[1], b[2], b[3], smaddr(&M[row][((eg + (row >> 3)) & 3) << 3]));
}

__device__ __forceinline__ void mma_bf16(float* d, const u32* a, u32 b0, u32 b1) {
    asm volatile(
        "mma.sync.aligned.m16n8k16.row.col.f32.bf16.bf16.f32 "
        "{%0,%1,%2,%3}, {%4,%5,%6,%7}, {%8,%9}, {%0,%1,%2,%3};"
        : "+f"(d[0]), "+f"(d[1]), "+f"(d[2]), "+f"(d[3])
        : "r"(a[0]), "r"(a[1]), "r"(a[2]), "r"(a[3]), "r"(b0), "r"(b1));
}

__device__ __forceinline__ void split_st(bf16* hp, bf16* lp, size_t idx, float2 v) {
    bf16 h0 = __float2bfloat16(v.x), h1 = __float2bfloat16(v.y);
    *(bf162*)(hp + idx) = bf162(h0, h1);
    *(bf162*)(lp + idx) = bf162(__float2bfloat16(v.x - __bfloat162float(h0)),
                                __float2bfloat16(v.y - __bfloat162float(h1)));
}

// pack two fp32 into bf16x2 {lo=x, hi=y} plus residual pair
__device__ __forceinline__ void split2(float x, float y, u32& hi, u32& lo) {
    float xh = __bfloat162float(__float2bfloat16(x));
    float yh = __bfloat162float(__float2bfloat16(y));
    asm("cvt.rn.bf16x2.f32 %0, %1, %2;" : "=r"(hi) : "f"(yh), "f"(xh));
    asm("cvt.rn.bf16x2.f32 %0, %1, %2;" : "=r"(lo) : "f"(y - yh), "f"(x - xh));
}
__device__ __forceinline__ u32 pack_bf(float x, float y) {
    u32 r; asm("cvt.rn.bf16x2.f32 %0, %1, %2;" : "=r"(r) : "f"(y), "f"(x)); return r;
}

// fill one 64-row tile (hi or lo selected by sel) from [(rowbase+rr)*32] source
__device__ __forceinline__ void fill_tile(
    bf16 (*Dh)[ASTR], bf16 (*Dl)[ASTR],
    const bf16* __restrict__ srcH, const bf16* __restrict__ srcL,
    size_t rowbase, int rr, int sel, int rsw)
{
    const uint4* s = (const uint4*)((sel ? srcL : srcH) + (rowbase + rr) * 32);
    bf16 (*D)[ASTR] = sel ? Dl : Dh;
#pragma unroll
    for (int g = 0; g < 4; g++) {
        int pg = ((g + rsw) & 3) << 3;
        *(uint4*)&D[rr][pg] = s[g];
    }
}

// ================= proj/out HMMA kernel =================
struct HArgs {
    const bf16 *Ahi, *Alo;
    const bf16 *Bh, *Bl;
    float* Ofp;
    bf16 *Oh[7], *Ol[7];
    int mode;
};

__global__ __launch_bounds__(128) void hmma_kernel(HArgs args)
{
    __shared__ __align__(16) bf16 Ah[128][ASTR], Al[128][ASTR];
    __shared__ __align__(16) bf16 Bhs[64][ASTR], Bls[64][ASTR];
    const int x = blockIdx.x, y = blockIdx.y;
    int set, col0, TL, qoff, m0;
    if (args.mode == 0) {
        if (x < 56) { set = y >> 2; col0 = (y & 3) * 64; TL = Tt; qoff = S1c; m0 = x * 128; }
        else {
            if (y >= 12) return;
            set = 4 + (y >> 2); col0 = (y & 3) * 64; TL = S1c; qoff = 0; m0 = (x - 56) * 128;
        }
    } else { set = 7; col0 = y * 64; TL = Qq; qoff = 0; m0 = x * 128; }

    const int tid = threadIdx.x;
    const int warp = tid >> 5, lane = tid & 31;

    float acc[2][8][4];
#pragma unroll
    for (int mf = 0; mf < 2; mf++)
#pragma unroll
        for (int nf = 0; nf < 8; nf++)
#pragma unroll
            for (int j = 0; j < 4; j++) acc[mf][nf][j] = 0.f;

    int t = m0 + tid;
    int ab = t / TL;
    size_t arow = ((size_t)ab * Qq + qoff + (t - ab * TL)) * 256;
    const int br = tid & 63;
    const bf16* Bsrc = ((tid < 64) ? args.Bh : args.Bl) + (size_t)set * 65536 + (size_t)(col0 + br) * 256;
    const int rswA = (tid >> 3) & 3;
    const int rswB = (br >> 3) & 3;

    for (int k0 = 0; k0 < 256; k0 += 32) {
        if (k0) __syncthreads();
        const uint4* sAh = (const uint4*)(args.Ahi + arow + k0);
        const uint4* sAl = (const uint4*)(args.Alo + arow + k0);
#pragma unroll
        for (int g = 0; g < 4; g++) {
            int pg = ((g + rswA) & 3) << 3;
            *(uint4*)&Ah[tid][pg] = sAh[g];
            *(uint4*)&Al[tid][pg] = sAl[g];
        }
        {
            const uint4* sB = (const uint4*)(Bsrc + k0);
            bf16 (*Bd)[ASTR] = (tid < 64) ? Bhs : Bls;
#pragma unroll
            for (int g = 0; g < 4; g++) {
                int pg = ((g + rswB) & 3) << 3;
                *(uint4*)&Bd[br][pg] = sB[g];
            }
        }
        __syncthreads();
#pragma unroll
        for (int ks = 0; ks < 2; ks++) {
            u32 ah[2][4], al[2][4];
            ldA(ah[0], Ah, warp * 32,      ks, lane);
            ldA(ah[1], Ah, warp * 32 + 16, ks, lane);
            ldA(al[0], Al, warp * 32,      ks, lane);
            ldA(al[1], Al, warp * 32 + 16, ks, lane);
#pragma unroll
            for (int np = 0; np < 4; np++) {
                u32 bh[4], bl[4];
                ldB(bh, Bhs, np * 16, ks, lane);
                ldB(bl, Bls, np * 16, ks, lane);
#pragma unroll
                for (int q = 0; q < 2; q++) {
                    int nf = np * 2 + q;
#pragma unroll
                    for (int mf = 0; mf < 2; mf++) {
                        mma_bf16(acc[mf][nf], ah[mf], bh[2*q], bh[2*q+1]);
                        mma_bf16(acc[mf][nf], ah[mf], bl[2*q], bl[2*q+1]);
                        mma_bf16(acc[mf][nf], al[mf], bh[2*q], bh[2*q+1]);
                    }
                }
            }
        }
    }

#pragma unroll
    for (int mf = 0; mf < 2; mf++) {
#pragma unroll
        for (int nf = 0; nf < 8; nf++) {
            int lc = nf * 8 + (lane & 3) * 2;
            int t0 = m0 + warp * 32 + mf * 16 + (lane >> 2);
            int t1 = t0 + 8;
            float2 v0 = make_float2(acc[mf][nf][0], acc[mf][nf][1]);
            float2 v1 = make_float2(acc[mf][nf][2], acc[mf][nf][3]);
            if (args.mode == 0) {
                int c = col0 + lc;
                int h = c >> 5, e = c & 31;
                int b0i = t0 / TL, n0i = t0 - b0i * TL;
                int b1i = t1 / TL, n1i = t1 - b1i * TL;
                size_t i0 = (((size_t)h * Bb + b0i) * TL + n0i) * 32 + e;
                size_t i1 = (((size_t)h * Bb + b1i) * TL + n1i) * 32 + e;
                split_st(args.Oh[set], args.Ol[set], i0, v0);
                split_st(args.Oh[set], args.Ol[set], i1, v1);
            } else {
                int d = col0 + lc;
                *(float2*)(args.Ofp + (size_t)t0 * 256 + d) = v0;
                *(float2*)(args.Ofp + (size_t)t1 * 256 + d) = v1;
            }
        }
    }
}

// ================= QK^T HMMA (stationary-tile loop version) =================
struct QKArgs {
    const bf16 *Q1h, *Q1l, *Q0h, *Q0l, *Qsh, *Qsl;
    const bf16 *Kch, *Kcl, *Ksh, *Ksl;
    float *P1, *P2, *P3;
};

__device__ __forceinline__ void qk_tile(
    const bf16 (*Qhs)[ASTR], const bf16 (*Qls)[ASTR],
    const bf16 (*Khs)[ASTR], const bf16 (*Kls)[ASTR],
    float* Sb, int Nk, int row0, int col0, int warp, int lane)
{
    float acc[8][4];
#pragma unroll
    for (int nf = 0; nf < 8; nf++)
#pragma unroll
        for (int j = 0; j < 4; j++) acc[nf][j] = 0.f;
#pragma unroll
    for (int ks = 0; ks < 2; ks++) {
        u32 ah[4], al[4];
        ldA(ah, Qhs, warp * 16, ks, lane);
        ldA(al, Qls, warp * 16, ks, lane);
#pragma unroll
        for (int np = 0; np < 4; np++) {
            u32 bh[4], bl[4];
            ldB(bh, Khs, np * 16, ks, lane);
            ldB(bl, Kls, np * 16, ks, lane);
#pragma unroll
            for (int q = 0; q < 2; q++) {
                int nf = np * 2 + q;
                mma_bf16(acc[nf], ah, bh[2*q], bh[2*q+1]);
                mma_bf16(acc[nf], ah, bl[2*q], bl[2*q+1]);
                mma_bf16(acc[nf], al, bh[2*q], bh[2*q+1]);
            }
        }
    }
#pragma unroll
    for (int nf = 0; nf < 8; nf++) {
        int col = col0 + nf * 8 + (lane & 3) * 2;
        int r0 = row0 + warp * 16 + (lane >> 2);
        *(float2*)(Sb + (size_t)r0 * Nk + col)       = make_float2(acc[nf][0], acc[nf][1]);
        *(float2*)(Sb + (size_t)(r0 + 8) * Nk + col) = make_float2(acc[nf][2], acc[nf][3]);
    }
}

__global__ __launch_bounds__(128) void qk_hmma(QKArgs a)
{
    __shared__ __align__(16) bf16 Qhs[64][ASTR], Qls[64][ASTR];
    __shared__ __align__(16) bf16 Khs[64][ASTR], Kls[64][ASTR];
    const int x = blockIdx.x, z = blockIdx.y;
    const int tid = threadIdx.x;
    const int warp = tid >> 5, lane = tid & 31;
    const int rr = tid & 63;
    const int sel = tid >> 6;
    const int rsw = (rr >> 3) & 3;

    if (x < 7) {
        fill_tile(Qhs, Qls, a.Q1h, a.Q1l, (size_t)z * Tt + x * 64, rr, sel, rsw);
        float* Sb = a.P1 + (size_t)z * Tt * Tt;
        for (int mt = 0; mt < 7; mt++) {
            if (mt) __syncthreads();
            fill_tile(Khs, Kls, a.Kch, a.Kcl, (size_t)z * Tt + mt * 64, rr, sel, rsw);
            __syncthreads();
            qk_tile(Qhs, Qls, Khs, Kls, Sb, Tt, x * 64, mt * 64, warp, lane);
        }
    } else if (x == 7) {
        fill_tile(Khs, Kls, a.Ksh, a.Ksl, (size_t)z * S1c, rr, sel, rsw);
        float* Sb = a.P2 + (size_t)z * Tt * S1c;
        for (int qt = 0; qt < 7; qt++) {
            if (qt) __syncthreads();
            fill_tile(Qhs, Qls, a.Q0h, a.Q0l, (size_t)z * Tt + qt * 64, rr, sel, rsw);
            __syncthreads();
            qk_tile(Qhs, Qls, Khs, Kls, Sb, S1c, qt * 64, 0, warp, lane);
        }
    } else {
        fill_tile(Qhs, Qls, a.Qsh, a.Qsl, (size_t)z * S1c, rr, sel, rsw);
        float* Sb = a.P3 + (size_t)z * S1c * Tt;
        for (int mt = 0; mt < 7; mt++) {
            if (mt) __syncthreads();
            fill_tile(Khs, Kls, a.Kch, a.Kcl, (size_t)z * Tt + mt * 64, rr, sel, rsw);
            __syncthreads();
            qk_tile(Qhs, Qls, Khs, Kls, Sb, Tt, 0, mt * 64, warp, lane);
        }
    }
}

// ================= tensor-core fuse MLP + softmax =================
// Per 16-pair group: L1 = X[16,16]@W1 (6 MMAs, 3-term), relu, L2 @W2 (3 MMAs).
// Accumulator fragment of L1 doubles as A fragment of L2 (D->A layout identity).
struct FuseW {
    u32 w1h[2][2], w1l[2][2];   // [j-half][b0/b1]
    u32 w2h[2], w2l[2];
    float bj0, bj1, bj8, bj9, bh0, bh1;
};

__device__ __forceinline__ void fuse_load_w(
    FuseW& fw, const float* W1, const float* b1,
    const float* W2, const float* b2, int lane)
{
    int t = lane & 3, g = lane >> 2;
#pragma unroll
    for (int hf = 0; hf < 2; hf++) {
        int J = hf * 8 + g;
        split2(W1[(2*t)*16 + J],     W1[(2*t+1)*16 + J], fw.w1h[hf][0], fw.w1l[hf][0]);
        split2(W1[(8+2*t)*16 + J],   W1[(9+2*t)*16 + J], fw.w1h[hf][1], fw.w1l[hf][1]);
    }
    split2(W2[(2*t)*8 + g],   W2[(2*t+1)*8 + g], fw.w2h[0], fw.w2l[0]);
    split2(W2[(8+2*t)*8 + g], W2[(9+2*t)*8 + g], fw.w2h[1], fw.w2l[1]);
    fw.bj0 = b1[2*t]; fw.bj1 = b1[2*t+1];
    fw.bj8 = b1[8+2*t]; fw.bj9 = b1[9+2*t];
    fw.bh0 = b2[2*t]; fw.bh1 = b2[2*t+1];
}

// compute one group: scores/aux rows given, m0 base; writes F regs (4 floats)
__device__ __forceinline__ void fuse_group(
    const FuseW& fw,
    const float* Sr0, const float* Sr1,
    const float* Ar0, const float* Ar1,
    int m0, int g, float* F)
{
    // build A fragments (hi/lo)
    u32 ah[4], al[4];
    split2(Sr0[m0 + g],     Sr1[m0 + g],     ah[0], al[0]);
    split2(Sr0[m0 + g + 8], Sr1[m0 + g + 8], ah[1], al[1]);
    split2(Ar0[m0 + g],     Ar1[m0 + g],     ah[2], al[2]);
    split2(Ar0[m0 + g + 8], Ar1[m0 + g + 8], ah[3], al[3]);
    // layer 1
    float D0[4] = {fw.bj0, fw.bj1, fw.bj0, fw.bj1};
    float D1[4] = {fw.bj8, fw.bj9, fw.bj8, fw.bj9};
    mma_bf16(D0, ah, fw.w1h[0][0], fw.w1h[0][1]);
    mma_bf16(D0, ah, fw.w1l[0][0], fw.w1l[0][1]);
    mma_bf16(D0, al, fw.w1h[0][0], fw.w1h[0][1]);
    mma_bf16(D1, ah, fw.w1h[1][0], fw.w1h[1][1]);
    mma_bf16(D1, ah, fw.w1l[1][0], fw.w1l[1][1]);
    mma_bf16(D1, al, fw.w1h[1][0], fw.w1h[1][1]);
    // relu + repack as layer-2 A operand
#pragma unroll
    for (int i = 0; i < 4; i++) { D0[i] = fmaxf(D0[i], 0.f); D1[i] = fmaxf(D1[i], 0.f); }
    u32 a2h[4], a2l[4];
    split2(D0[0], D0[1], a2h[0], a2l[0]);
    split2(D0[2], D0[3], a2h[1], a2l[1]);
    split2(D1[0], D1[1], a2h[2], a2l[2]);
    split2(D1[2], D1[3], a2h[3], a2l[3]);
    // layer 2
    F[0] = fw.bh0; F[1] = fw.bh1; F[2] = fw.bh0; F[3] = fw.bh1;
    mma_bf16(F, a2h, fw.w2h[0], fw.w2h[1]);
    mma_bf16(F, a2h, fw.w2l[0], fw.w2l[1]);
    mma_bf16(F, a2l, fw.w2h[0], fw.w2h[1]);
}

// jobs 1 & 3: NK=448. 224 threads (7 warps), one (b,n) per block.
__global__ __launch_bounds__(224) void fuse_big(
    const float* __restrict__ P1, const float* __restrict__ P3,
    const float* __restrict__ aux,
    bf16* __restrict__ P1hd, bf16* __restrict__ P1ld,
    bf16* __restrict__ P3hd, bf16* __restrict__ P3ld,
    const float* __restrict__ W1, const float* __restrict__ b1,
    const float* __restrict__ W2, const float* __restrict__ b2)
{
    __shared__ __align__(16) float fs[8][448];
    const int tid = threadIdx.x;
    const int warp = tid >> 5, lane = tid & 31;
    const int t = lane & 3, g = lane >> 2;

    int blk = blockIdx.x;
    const float* S; bf16 *Ph, *Pl;
    int b, n, Nq, qn;
    if (blk < 16 * 448) {
        b = blk / 448; n = blk % 448;
        S = P1; Ph = P1hd; Pl = P1ld; Nq = Tt; qn = S1c;
    } else {
        blk -= 16 * 448;
        b = blk / 64; n = blk % 64;
        S = P3; Ph = P3hd; Pl = P3ld; Nq = S1c; qn = 0;
    }

    FuseW fw;
    fuse_load_w(fw, W1, b1, W2, b2, lane);

    const float* Sr0 = S + ((size_t)((2*t)   * 16 + b) * Nq + n) * 448;
    const float* Sr1 = S + ((size_t)((2*t+1) * 16 + b) * Nq + n) * 448;
    const float* Ar0 = aux + ((size_t)((2*t)   * 16 + b) * 512 + qn + n) * 512 + S1c;
    const float* Ar1 = aux + ((size_t)((2*t+1) * 16 + b) * 512 + qn + n) * 512 + S1c;

#pragma unroll
    for (int gi = 0; gi < 4; gi++) {
        int m0 = (warp + 7 * gi) * 16;
        float F[4];
        fuse_group(fw, Sr0, Sr1, Ar0, Ar1, m0, g, F);
        fs[2*t]   [m0 + g]     = F[0];
        fs[2*t+1] [m0 + g]     = F[1];
        fs[2*t]   [m0 + g + 8] = F[2];
        fs[2*t+1] [m0 + g + 8] = F[3];
    }
    __syncthreads();

    for (int row = warp; row < 8; row += 7) {
        float* frow = fs[row];
        float mx = -3.0e38f;
        for (int m = lane; m < 448; m += 32) mx = fmaxf(mx, frow[m]);
#pragma unroll
        for (int o = 16; o > 0; o >>= 1) mx = fmaxf(mx, __shfl_xor_sync(0xffffffffu, mx, o));
        float sum = 0.f;
        for (int m = lane; m < 448; m += 32) {
            float ev = __expf(frow[m] - mx);
            frow[m] = ev;
            sum += ev;
        }
#pragma unroll
        for (int o = 16; o > 0; o >>= 1) sum += __shfl_xor_sync(0xffffffffu, sum, o);
        float inv = 1.f / sum;
        size_t base = ((size_t)(row * 16 + b) * Nq + n) * 448;
        for (int m = lane; m < 448; m += 32) {
            float p = frow[m] * inv;
            bf16 h = __float2bfloat16(p);
            Ph[base + m] = h;
            Pl[base + m] = __float2bfloat16(p - __bfloat162float(h));
        }
    }
}

// job 2: NK=64. 256 threads (8 warps); warp w owns n-row n0+w.
__global__ __launch_bounds__(256) void fuse_small(
    const float* __restrict__ P2, const float* __restrict__ aux,
    bf16* __restrict__ P2hd, bf16* __restrict__ P2ld,
    const float* __restrict__ W1, const float* __restrict__ b1,
    const float* __restrict__ W2, const float* __restrict__ b2)
{
    __shared__ __align__(16) float fs[8][8][64];
    const int tid = threadIdx.x;
    const int warp = tid >> 5, lane = tid & 31;
    const int t = lane & 3, g = lane >> 2;

    const int b  = blockIdx.x / 56;
    const int n0 = (blockIdx.x % 56) * 8;
    const int n  = n0 + warp;

    FuseW fw;
    fuse_load_w(fw, W1, b1, W2, b2, lane);

    const float* Sr0 = P2 + ((size_t)((2*t)   * 16 + b) * Tt + n) * 64;
    const float* Sr1 = P2 + ((size_t)((2*t+1) * 16 + b) * Tt + n) * 64;
    const float* Ar0 = aux + ((size_t)((2*t)   * 16 + b) * 512 + S1c + n) * 512;
    const float* Ar1 = aux + ((size_t)((2*t+1) * 16 + b) * 512 + S1c + n) * 512;

#pragma unroll
    for (int gi = 0; gi < 4; gi++) {
        int m0 = gi * 16;
        float F[4];
        fuse_group(fw, Sr0, Sr1, Ar0, Ar1, m0, g, F);
        fs[warp][2*t]   [m0 + g]     = F[0];
        fs[warp][2*t+1] [m0 + g]     = F[1];
        fs[warp][2*t]   [m0 + g + 8] = F[2];
        fs[warp][2*t+1] [m0 + g + 8] = F[3];
    }
    __syncwarp();

#pragma unroll
    for (int hr = 0; hr < 8; hr++) {
        float f1 = fs[warp][hr][lane];
        float f2 = fs[warp][hr][lane + 32];
        float mx = fmaxf(f1, f2);
#pragma unroll
        for (int o = 16; o > 0; o >>= 1) mx = fmaxf(mx, __shfl_xor_sync(0xffffffffu, mx, o));
        float e1 = __expf(f1 - mx), e2 = __expf(f2 - mx);
        float sum = e1 + e2;
#pragma unroll
        for (int o = 16; o > 0; o >>= 1) sum += __shfl_xor_sync(0xffffffffu, sum, o);
        float inv = 1.f / sum;
        float p1 = e1 * inv, p2 = e2 * inv;
        size_t base = ((size_t)(hr * 16 + b) * Tt + n) * 64;
        bf16 h1 = __float2bfloat16(p1), h2 = __float2bfloat16(p2);
        P2hd[base + lane]      = h1;
        P2ld[base + lane]      = __float2bfloat16(p1 - __bfloat162float(h1));
        P2hd[base + lane + 32] = h2;
        P2ld[base + lane + 32] = __float2bfloat16(p2 - __bfloat162float(h2));
    }
}

// ================= merged AV HMMA (single launch, split epilogue) =================
struct AVArgs {
    const bf16 *P1h, *P1l, *P2h, *P2l, *P3h, *P3l;
    const bf16 *Vch, *Vcl, *Vsh, *Vsl;
    bf16 *Hhi, *Hlo;
};
__global__ __launch_bounds__(128) void av_hmma(AVArgs a)
{
    __shared__ __align__(16) bf16 Phs[64][ASTR], Pls[64][ASTR];
    __shared__ __align__(16) bf16 Vhs[32][ASTR], Vls[32][ASTR];
    const int x = blockIdx.x, z = blockIdx.y;
    const int hh = z >> 4, bb = z & 15;
    const int tid = threadIdx.x;
    const int warp = tid >> 5, lane = tid & 31;

    int n0, qoff, nchunks;
    if (x < 7) { n0 = x * 64; qoff = S1c; nchunks = 16; }
    else       { n0 = 0;      qoff = 0;   nchunks = 14; }

    float acc[4][4];
#pragma unroll
    for (int nf = 0; nf < 4; nf++)
#pragma unroll
        for (int j = 0; j < 4; j++) acc[nf][j] = 0.f;

    for (int c = 0; c < nchunks; c++) {
        if (c) __syncthreads();
        const bf16 *Ph, *Pl, *Vh, *Vl;
        size_t prow; int pstride; size_t vrow;
        if (x < 7) {
            if (c < 14) {
                Ph = a.P1h; Pl = a.P1l; Vh = a.Vch; Vl = a.Vcl;
                pstride = Tt;  prow = ((size_t)z * Tt + n0) * Tt + c * 32;
                vrow = (size_t)z * Tt + c * 32;
            } else {
                Ph = a.P2h; Pl = a.P2l; Vh = a.Vsh; Vl = a.Vsl;
                pstride = S1c; prow = ((size_t)z * Tt + n0) * S1c + (c - 14) * 32;
                vrow = (size_t)z * S1c + (c - 14) * 32;
            }
        } else {
            Ph = a.P3h; Pl = a.P3l; Vh = a.Vch; Vl = a.Vcl;
            pstride = Tt;  prow = ((size_t)z * S1c) * Tt + c * 32;
            vrow = (size_t)z * Tt + c * 32;
        }
        {
            int rr = tid & 63;
            int sel = tid >> 6;
            int rsw = (rr >> 3) & 3;
            const uint4* ps = (const uint4*)((sel ? Pl : Ph) + prow + (size_t)rr * pstride);
            bf16 (*Pd)[ASTR] = sel ? Pls : Phs;
#pragma unroll
            for (int g = 0; g < 4; g++) {
                int pg = ((g + rsw) & 3) << 3;
                *(uint4*)&Pd[rr][pg] = ps[g];
            }
        }
        if (tid < 64) {
            int rr = tid & 31;
            int sel = tid >> 5;
            int rsw = (rr >> 3) & 3;
            const uint4* vs = (const uint4*)((sel ? Vl : Vh) + (vrow + rr) * 32);
            bf16 (*Vd)[ASTR] = sel ? Vls : Vhs;
#pragma unroll
            for (int g = 0; g < 4; g++) {
                int pg = ((g + rsw) & 3) << 3;
                *(uint4*)&Vd[rr][pg] = vs[g];
            }
        }
        __syncthreads();
#pragma unroll
        for (int ks = 0; ks < 2; ks++) {
            u32 ah[4], al[4];
            ldA(ah, Phs, warp * 16, ks, lane);
            ldA(al, Pls, warp * 16, ks, lane);
#pragma unroll
            for (int np = 0; np < 2; np++) {
                u32 bh[4], bl[4];
                ldBt(bh, Vhs, np, ks, lane);
                ldBt(bl, Vls, np, ks, lane);
#pragma unroll
                for (int q = 0; q < 2; q++) {
                    int nf = np * 2 + q;
                    mma_bf16(acc[nf], ah, bh[2*q], bh[2*q+1]);
                    mma_bf16(acc[nf], ah, bl[2*q], bl[2*q+1]);
                    mma_bf16(acc[nf], al, bh[2*q], bh[2*q+1]);
                }
            }
        }
    }
#pragma unroll
    for (int nf = 0; nf < 4; nf++) {
        int e = nf * 8 + (lane & 3) * 2;
        int r0 = n0 + warp * 16 + (lane >> 2);
#pragma unroll
        for (int half = 0; half < 2; half++) {
            int rq = r0 + half * 8;
            float2 v = half ? make_float2(acc[nf][2], acc[nf][3])
                            : make_float2(acc[nf][0], acc[nf][1]);
            size_t idx = ((size_t)(bb * Qq + qoff + rq)) * 256 + hh * 32 + e;
            split_st(a.Hhi, a.Hlo, idx, v);
        }
    }
}

// ---------------- launch ----------------
extern "C" void kernel_launch(void* const* d_in, const int* in_sizes, int n_in,
                              void* d_out, int out_size)
{
    const float* h_fea      = (const float*)d_in[0];
    const float* aux        = (const float*)d_in[1];
    const float* Wq_custom  = (const float*)d_in[2];
    const float* Wq_custom1 = (const float*)d_in[3];
    const float* Wk_custom  = (const float*)d_in[4];
    const float* Wv_custom  = (const float*)d_in[5];
    const float* Wq_charge1 = (const float*)d_in[6];
    const float* Wk_charge  = (const float*)d_in[7];
    const float* Wv_charge  = (const float*)d_in[8];
    const float* W1         = (const float*)d_in[9];
    const float* b1         = (const float*)d_in[10];
    const float* W2         = (const float*)d_in[11];
    const float* b2         = (const float*)d_in[12];
    const float* W_out      = (const float*)d_in[13];
    float* out = (float*)d_out;

    float *P1, *P2, *P3;
    bf16 *Xhi, *Xlo, *Hhi, *Hlo, *Wbh, *Wbl;
    bf16 *Q1h, *Q1l, *Q0h, *Q0l, *Kch, *Kcl, *Vch, *Vcl;
    bf16 *Qsh, *Qsl, *Ksh, *Ksl, *Vsh, *Vsl;
    bf16 *P1h, *P1l, *P2h, *P2l, *P3h, *P3l;
    cudaGetSymbolAddress((void**)&P1, g_P1);
    cudaGetSymbolAddress((void**)&P2, g_P2);
    cudaGetSymbolAddress((void**)&P3, g_P3);
    cudaGetSymbolAddress((void**)&Xhi, g_Xhi);
    cudaGetSymbolAddress((void**)&Xlo, g_Xlo);
    cudaGetSymbolAddress((void**)&Hhi, g_Hhi);
    cudaGetSymbolAddress((void**)&Hlo, g_Hlo);
    cudaGetSymbolAddress((void**)&Wbh, g_Wbh);
    cudaGetSymbolAddress((void**)&Wbl, g_Wbl);
    cudaGetSymbolAddress((void**)&Q1h, g_Q1h);  cudaGetSymbolAddress((void**)&Q1l, g_Q1l);
    cudaGetSymbolAddress((void**)&Q0h, g_Q0h);  cudaGetSymbolAddress((void**)&Q0l, g_Q0l);
    cudaGetSymbolAddress((void**)&Kch, g_Kch);  cudaGetSymbolAddress((void**)&Kcl, g_Kcl);
    cudaGetSymbolAddress((void**)&Vch, g_Vch);  cudaGetSymbolAddress((void**)&Vcl, g_Vcl);
    cudaGetSymbolAddress((void**)&Qsh, g_Qsh);  cudaGetSymbolAddress((void**)&Qsl, g_Qsl);
    cudaGetSymbolAddress((void**)&Ksh, g_Ksh);  cudaGetSymbolAddress((void**)&Ksl, g_Ksl);
    cudaGetSymbolAddress((void**)&Vsh, g_Vsh);  cudaGetSymbolAddress((void**)&Vsl, g_Vsl);
    cudaGetSymbolAddress((void**)&P1h, g_P1h);  cudaGetSymbolAddress((void**)&P1l, g_P1l);
    cudaGetSymbolAddress((void**)&P2h, g_P2h);  cudaGetSymbolAddress((void**)&P2l, g_P2l);
    cudaGetSymbolAddress((void**)&P3h, g_P3h);  cudaGetSymbolAddress((void**)&P3l, g_P3l);

    // 1. input/weight splits
    cvt_split_kernel<<<(Bb*Qq*Dd/4 + 255)/256, 256>>>(h_fea, Xhi, Xlo, Bb*Qq*Dd/4);
    WArgs wa;
    wa.W[0] = Wq_custom1; wa.W[1] = Wq_custom; wa.W[2] = Wk_custom; wa.W[3] = Wv_custom;
    wa.W[4] = Wq_charge1; wa.W[5] = Wk_charge; wa.W[6] = Wv_charge; wa.W[7] = W_out;
    cvt_w_kernel<<<8*256*256/256, 256>>>(wa, Wbh, Wbl);

    // 2. merged projections
    HArgs hp;
    hp.Ahi = Xhi; hp.Alo = Xlo; hp.Bh = Wbh; hp.Bl = Wbl;
    hp.Ofp = nullptr; hp.mode = 0;
    hp.Oh[0] = Q1h; hp.Ol[0] = Q1l;
    hp.Oh[1] = Q0h; hp.Ol[1] = Q0l;
    hp.Oh[2] = Kch; hp.Ol[2] = Kcl;
    hp.Oh[3] = Vch; hp.Ol[3] = Vcl;
    hp.Oh[4] = Qsh; hp.Ol[4] = Qsl;
    hp.Oh[5] = Ksh; hp.Ol[5] = Ksl;
    hp.Oh[6] = Vsh; hp.Ol[6] = Vsl;
    hmma_kernel<<<dim3(64, 16), 128>>>(hp);

    // 3. QK^T
    QKArgs qa;
    qa.Q1h = Q1h; qa.Q1l = Q1l; qa.Q0h = Q0h; qa.Q0l = Q0l; qa.Qsh = Qsh; qa.Qsl = Qsl;
    qa.Kch = Kch; qa.Kcl = Kcl; qa.Ksh = Ksh; qa.Ksl = Ksl;
    qa.P1 = P1; qa.P2 = P2; qa.P3 = P3;
    qk_hmma<<<dim3(9, 128), 128>>>(qa);

    // 4. tensor-core fuse MLP + softmax
    fuse_big<<<16*448 + 16*64, 224>>>(P1, P3, aux, P1h, P1l, P3h, P3l, W1, b1, W2, b2);
    fuse_small<<<16*56, 256>>>(P2, aux, P2h, P2l, W1, b1, W2, b2);

    // 5. merged AV -> head splits directly
    AVArgs aa;
    aa.P1h = P1h; aa.P1l = P1l; aa.P2h = P2h; aa.P2l = P2l; aa.P3h = P3h; aa.P3l = P3l;
    aa.Vch = Vch; aa.Vcl = Vcl; aa.Vsh = Vsh; aa.Vsl = Vsl;
    aa.Hhi = Hhi; aa.Hlo = Hlo;
    av_hmma<<<dim3(8, 128), 128>>>(aa);

    // 6. output GEMM
    HArgs ho;
    ho.Ahi = Hhi; ho.Alo = Hlo; ho.Bh = Wbh; ho.Bl = Wbl;
    ho.Ofp = out; ho.mode = 1;
    for (int i = 0; i < 7; i++) { ho.Oh[i] = nullptr; ho.Ol[i] = nullptr; }
    hmma_kernel<<<dim3(64, 4), 128>>>(ho);
}